// round 1
// baseline (speedup 1.0000x reference)
#include <cuda_runtime.h>

#define NN   100000
#define DEG  16
#define DIM  128
#define BM   128
#define SMS  132   // padded smem row stride (floats), keeps float4 alignment

// Scratch (no allocations allowed in kernel_launch — module globals are the sanctioned path)
__device__ float g_z [(size_t)NN * DIM];
__device__ float g_zi[(size_t)NN * DIM];
__device__ float g_h1[(size_t)NN * DIM];
__device__ float g_ssrc[NN];
__device__ float g_sdst[NN];

// z = h @ W^T ; zi = h @ U^T ; ssrc = z @ a[0:128] ; sdst = z @ a[128:256]
// Block: 128 rows x all 128 cols, 256 threads (16x16), 8x8 register tile.
// Cols per thread: tx + 16*j  (stride-16 to keep smem b-loads near conflict-free)
__global__ __launch_bounds__(256, 1)
void gemm_dual_kernel(const float* __restrict__ h, const float* __restrict__ W,
                      const float* __restrict__ U, const float* __restrict__ avec,
                      float* __restrict__ z, float* __restrict__ zi,
                      float* __restrict__ ssrc, float* __restrict__ sdst, int n)
{
    extern __shared__ float smem[];
    float* hs = smem;                 // [BM][SMS]
    float* ws = smem + BM * SMS;      // [DIM][SMS]

    const int tid  = threadIdx.x;
    const int tx   = tid & 15;
    const int ty   = tid >> 4;
    const int row0 = blockIdx.x * BM;

    // Load h tile [128][128] -> hs (coalesced float4)
    #pragma unroll
    for (int i = 0; i < 16; i++) {
        int idx = tid + i * 256;          // 0..4095
        int m   = idx >> 5;               // row in tile
        int q   = idx & 31;               // float4 index
        int gr  = row0 + m;
        float4 v = make_float4(0.f, 0.f, 0.f, 0.f);
        if (gr < n) v = *(const float4*)(h + (size_t)gr * DIM + q * 4);
        *(float4*)(hs + m * SMS + q * 4) = v;
    }

    for (int pass = 0; pass < 2; pass++) {
        const float* Mt = pass ? U : W;
        __syncthreads();                  // hs ready / ws drained from prev pass
        #pragma unroll
        for (int i = 0; i < 16; i++) {
            int idx = tid + i * 256;
            int cc  = idx >> 5;
            int q   = idx & 31;
            *(float4*)(ws + cc * SMS + q * 4) = *(const float4*)(Mt + cc * DIM + q * 4);
        }
        __syncthreads();

        float acc[8][8];
        #pragma unroll
        for (int i = 0; i < 8; i++)
            #pragma unroll
            for (int j = 0; j < 8; j++) acc[i][j] = 0.f;

        #pragma unroll 4
        for (int k = 0; k < DIM; k++) {
            float av[8], bv[8];
            #pragma unroll
            for (int i = 0; i < 8; i++) av[i] = hs[(ty * 8 + i) * SMS + k];   // broadcast
            #pragma unroll
            for (int j = 0; j < 8; j++) bv[j] = ws[(tx + 16 * j) * SMS + k];  // ~2-way worst
            #pragma unroll
            for (int i = 0; i < 8; i++)
                #pragma unroll
                for (int j = 0; j < 8; j++)
                    acc[i][j] = fmaf(av[i], bv[j], acc[i][j]);
        }

        float* dst = pass ? zi : z;
        if (pass == 0) {
            float asrc[8], adst[8];
            #pragma unroll
            for (int j = 0; j < 8; j++) {
                asrc[j] = avec[tx + 16 * j];
                adst[j] = avec[DIM + tx + 16 * j];
            }
            #pragma unroll
            for (int i = 0; i < 8; i++) {
                int r = row0 + ty * 8 + i;
                float ps = 0.f, pd = 0.f;
                #pragma unroll
                for (int j = 0; j < 8; j++) {
                    ps = fmaf(acc[i][j], asrc[j], ps);
                    pd = fmaf(acc[i][j], adst[j], pd);
                }
                // reduce over the 16 tx lanes (xor<=8 stays within each half-warp group)
                #pragma unroll
                for (int o = 8; o > 0; o >>= 1) {
                    ps += __shfl_xor_sync(0xffffffffu, ps, o);
                    pd += __shfl_xor_sync(0xffffffffu, pd, o);
                }
                if (r < n) {
                    if (tx == 0) { ssrc[r] = ps; sdst[r] = pd; }
                    #pragma unroll
                    for (int j = 0; j < 8; j++)
                        dst[(size_t)r * DIM + tx + 16 * j] = acc[i][j];
                }
            }
        } else {
            #pragma unroll
            for (int i = 0; i < 8; i++) {
                int r = row0 + ty * 8 + i;
                if (r < n) {
                    #pragma unroll
                    for (int j = 0; j < 8; j++)
                        dst[(size_t)r * DIM + tx + 16 * j] = acc[i][j];
                }
            }
        }
    }
}

// One warp per node. Edges of node i are [16i, 16i+16) because edge_dst = repeat(arange(N), DEG).
// Lanes 0..15: one edge score each; warp-shuffle softmax; all 32 lanes gather-accumulate
// cols [4*lane, 4*lane+4) over the 16 source rows (MLP=16 independent float4 loads).
__global__ __launch_bounds__(256)
void attn_agg_kernel(const float* __restrict__ z, const float* __restrict__ zi,
                     const float* __restrict__ ssrc, const float* __restrict__ sdst,
                     const float* __restrict__ edge_d, const int* __restrict__ edge_src,
                     const float* __restrict__ Wv, const float* __restrict__ avec,
                     float* __restrict__ out, int n)
{
    const int node = (blockIdx.x * blockDim.x + threadIdx.x) >> 5;
    const int lane = threadIdx.x & 31;
    if (node >= n) return;

    const float c = Wv[0] * avec[2 * DIM];   // t @ a_t collapses to c * edge_d[e]

    int   src = 0;
    float sc  = -1e30f;
    if (lane < DEG) {
        int e = node * DEG + lane;
        src   = edge_src[e];
        float s = ssrc[src] + sdst[node] + c * edge_d[e];
        sc = (s >= 0.f) ? s : 0.01f * s;     // leaky_relu
    }

    // max over the 16-lane group
    float m = sc;
    #pragma unroll
    for (int o = 8; o > 0; o >>= 1) m = fmaxf(m, __shfl_xor_sync(0xffffffffu, m, o));

    float ex = (lane < DEG) ? __expf(sc - m) : 0.f;
    float ssum = ex;
    #pragma unroll
    for (int o = 8; o > 0; o >>= 1) ssum += __shfl_xor_sync(0xffffffffu, ssum, o);
    float alpha = ex / ssum;                 // valid on lanes 0..15 (others unused)

    float al[DEG];
    int   sr[DEG];
    #pragma unroll
    for (int e = 0; e < DEG; e++) {
        al[e] = __shfl_sync(0xffffffffu, alpha, e);
        sr[e] = __shfl_sync(0xffffffffu, src,   e);
    }

    float4 acc = *(const float4*)(zi + (size_t)node * DIM + lane * 4);
    #pragma unroll
    for (int e = 0; e < DEG; e++) {
        float4 v = *(const float4*)(z + (size_t)sr[e] * DIM + lane * 4);
        acc.x = fmaf(al[e], v.x, acc.x);
        acc.y = fmaf(al[e], v.y, acc.y);
        acc.z = fmaf(al[e], v.z, acc.z);
        acc.w = fmaf(al[e], v.w, acc.w);
    }
    acc.x = fmaxf(acc.x, 0.f);
    acc.y = fmaxf(acc.y, 0.f);
    acc.z = fmaxf(acc.z, 0.f);
    acc.w = fmaxf(acc.w, 0.f);
    *(float4*)(out + (size_t)node * DIM + lane * 4) = acc;
}

extern "C" void kernel_launch(void* const* d_in, const int* in_sizes, int n_in,
                              void* d_out, int out_size)
{
    const float* attr   = (const float*)d_in[0];
    const float* edge_d = (const float*)d_in[1];
    const float* Wv1    = (const float*)d_in[2];
    const float* Ww1    = (const float*)d_in[3];
    const float* Wu1    = (const float*)d_in[4];
    const float* Wa1    = (const float*)d_in[5];
    const float* Wv2    = (const float*)d_in[6];
    const float* Ww2    = (const float*)d_in[7];
    const float* Wu2    = (const float*)d_in[8];
    const float* Wa2    = (const float*)d_in[9];
    const int*   esrc   = (const int*)d_in[10];
    float*       out    = (float*)d_out;

    float *zp, *zip, *h1p, *ssp, *sdp;
    cudaGetSymbolAddress((void**)&zp,  g_z);
    cudaGetSymbolAddress((void**)&zip, g_zi);
    cudaGetSymbolAddress((void**)&h1p, g_h1);
    cudaGetSymbolAddress((void**)&ssp, g_ssrc);
    cudaGetSymbolAddress((void**)&sdp, g_sdst);

    const int smem_sz = 2 * BM * SMS * (int)sizeof(float);   // 135168 B
    cudaFuncSetAttribute(gemm_dual_kernel,
                         cudaFuncAttributeMaxDynamicSharedMemorySize, smem_sz);

    const int grid_g = (NN + BM - 1) / BM;                   // 782
    const int grid_a = (NN * 32 + 255) / 256;                // 12500

    // Layer 1
    gemm_dual_kernel<<<grid_g, 256, smem_sz>>>(attr, Ww1, Wu1, Wa1, zp, zip, ssp, sdp, NN);
    attn_agg_kernel<<<grid_a, 256>>>(zp, zip, ssp, sdp, edge_d, esrc, Wv1, Wa1, h1p, NN);
    // Layer 2
    gemm_dual_kernel<<<grid_g, 256, smem_sz>>>(h1p, Ww2, Wu2, Wa2, zp, zip, ssp, sdp, NN);
    attn_agg_kernel<<<grid_a, 256>>>(zp, zip, ssp, sdp, edge_d, esrc, Wv2, Wa2, out, NN);
}

// round 4
// speedup vs baseline: 1.3854x; 1.3854x over previous
#include <cuda_runtime.h>
#include <cuda_bf16.h>
#include <cstdint>

#define NN   100000
#define DEG  16
#define DIM  128
#define BM   128
#define PADS 136                      // padded smem row stride (bf16 elems)

// ---------------- scratch (device globals: allocations are forbidden) ----------------
__device__ float g_z [(size_t)NN * DIM];
__device__ float g_zi[(size_t)NN * DIM];
__device__ float g_h1[(size_t)NN * DIM];
__device__ float g_ssrc[NN];
__device__ float g_sdst[NN];
// Pre-split weights, plain row-major bf16: [matrix: W1,U1,W2,U2][hi/lo][128*128]
__device__ __nv_bfloat16 g_wimg[4][2][DIM * DIM];
// Precomputed W^T a_src / W^T a_dst per layer: [layer][src/dst][128]
__device__ float g_wvec[2][2][DIM];

// ---------------- warp MMA helpers (base-target PTX: ldmatrix + mma.sync) ----------------
__device__ __forceinline__ uint32_t smem_to_u32(const void* p) {
    uint32_t a;
    asm("{ .reg .u64 t; cvta.to.shared.u64 t, %1; cvt.u32.u64 %0, t; }" : "=r"(a) : "l"(p));
    return a;
}
__device__ __forceinline__ void ldsm4(uint32_t* r, uint32_t addr) {
    asm volatile("ldmatrix.sync.aligned.m8n8.x4.shared.b16 {%0,%1,%2,%3}, [%4];"
                 : "=r"(r[0]), "=r"(r[1]), "=r"(r[2]), "=r"(r[3]) : "r"(addr));
}
__device__ __forceinline__ void mma16816(float* d, const uint32_t* a, const uint32_t* b) {
    asm volatile("mma.sync.aligned.m16n8k16.row.col.f32.bf16.bf16.f32 "
                 "{%0,%1,%2,%3}, {%4,%5,%6,%7}, {%8,%9}, {%0,%1,%2,%3};"
                 : "+f"(d[0]), "+f"(d[1]), "+f"(d[2]), "+f"(d[3])
                 : "r"(a[0]), "r"(a[1]), "r"(a[2]), "r"(a[3]), "r"(b[0]), "r"(b[1]));
}

// ---------------- weight conversion + score-vector precompute ----------------
__global__ void wconv_kernel(const float* __restrict__ W1, const float* __restrict__ U1,
                             const float* __restrict__ W2, const float* __restrict__ U2,
                             const float* __restrict__ Wa1, const float* __restrict__ Wa2)
{
    const int b = blockIdx.x;
    const float* src = (b == 0) ? W1 : (b == 1) ? U1 : (b == 2) ? W2 : U2;
    __nv_bfloat16* hi = g_wimg[b][0];
    __nv_bfloat16* lo = g_wimg[b][1];
    for (int c = threadIdx.x; c < DIM * DIM / 8; c += blockDim.x) {
        int row = c >> 4, cc = (c & 15) * 8;
        __align__(16) __nv_bfloat16 hb[8], lb[8];
        const float4* p = (const float4*)(src + row * DIM + cc);
        float4 v0 = p[0], v1 = p[1];
        float xs[8] = {v0.x, v0.y, v0.z, v0.w, v1.x, v1.y, v1.z, v1.w};
        #pragma unroll
        for (int j = 0; j < 8; j++) {
            __nv_bfloat16 h = __float2bfloat16(xs[j]);
            hb[j] = h;
            lb[j] = __float2bfloat16(xs[j] - __bfloat162float(h));
        }
        *(uint4*)(hi + row * DIM + cc) = *(const uint4*)hb;
        *(uint4*)(lo + row * DIM + cc) = *(const uint4*)lb;
    }
    // blocks 0/2 hold the W matrix of layer 0/1: build score vectors ws = W^T a_src, wd = W^T a_dst
    if ((b & 1) == 0) {
        const int layer = b >> 1;
        const float* Wa = layer ? Wa2 : Wa1;
        for (int k = threadIdx.x; k < DIM; k += blockDim.x) {
            float ws = 0.f, wd = 0.f;
            for (int nrow = 0; nrow < DIM; nrow++) {
                float w = src[nrow * DIM + k];
                ws = fmaf(Wa[nrow], w, ws);
                wd = fmaf(Wa[DIM + nrow], w, wd);
            }
            g_wvec[layer][0][k] = ws;
            g_wvec[layer][1][k] = wd;
        }
    }
}

// ---------------- tensor-core GEMM (legacy HMMA, bf16 3-split) ----------------
// z = h@W^T, zi = h@U^T, ssrc = h@wsv, sdst = h@wdv
// Block: 128x128 tile, 256 threads = 8 warps, warp tile 32(M)x64(N).
#define TILE (DIM * PADS)
#define SM_AH (0 * TILE)
#define SM_AL (1 * TILE)
#define SM_WH (2 * TILE)
#define SM_WL (3 * TILE)
#define SM_UH (4 * TILE)
#define SM_UL (5 * TILE)
#define SM_TOTAL_B (6 * TILE * 2)     // 208896 bytes

__global__ __launch_bounds__(256, 1)
void gemm_mma_kernel(const float* __restrict__ h,
                     const __nv_bfloat16* __restrict__ wh, const __nv_bfloat16* __restrict__ wl,
                     const __nv_bfloat16* __restrict__ uh, const __nv_bfloat16* __restrict__ ul,
                     const float* __restrict__ wsv, const float* __restrict__ wdv,
                     float* __restrict__ z, float* __restrict__ zi,
                     float* __restrict__ ssrc, float* __restrict__ sdst, int n)
{
    extern __shared__ __nv_bfloat16 smem[];
    const int tid  = threadIdx.x;
    const int lane = tid & 31;
    const int wid  = tid >> 5;
    const int row0 = blockIdx.x * BM;

    // ---- copy pre-split weights into padded smem (8-bf16 chunks) ----
    {
        const __nv_bfloat16* srcs[4] = {wh, wl, uh, ul};
        __nv_bfloat16* dsts[4] = {smem + SM_WH, smem + SM_WL, smem + SM_UH, smem + SM_UL};
        #pragma unroll
        for (int m = 0; m < 4; m++)
            for (int c = tid; c < DIM * DIM / 8; c += 256) {
                int row = c >> 4, cc = (c & 15) * 8;
                *(uint4*)(dsts[m] + row * PADS + cc) = *(const uint4*)(srcs[m] + row * DIM + cc);
            }
    }

    // ---- load + split A tile ----
    for (int c = tid; c < DIM * DIM / 8; c += 256) {
        int row = c >> 4, cc = (c & 15) * 8;
        int gr = row0 + row;
        __align__(16) __nv_bfloat16 hb[8], lb[8];
        if (gr < n) {
            const float4* p = (const float4*)(h + (size_t)gr * DIM + cc);
            float4 v0 = p[0], v1 = p[1];
            float xs[8] = {v0.x, v0.y, v0.z, v0.w, v1.x, v1.y, v1.z, v1.w};
            #pragma unroll
            for (int j = 0; j < 8; j++) {
                __nv_bfloat16 hv = __float2bfloat16(xs[j]);
                hb[j] = hv;
                lb[j] = __float2bfloat16(xs[j] - __bfloat162float(hv));
            }
        } else {
            #pragma unroll
            for (int j = 0; j < 8; j++) { hb[j] = __float2bfloat16(0.f); lb[j] = hb[j]; }
        }
        *(uint4*)(smem + SM_AH + row * PADS + cc) = *(const uint4*)hb;
        *(uint4*)(smem + SM_AL + row * PADS + cc) = *(const uint4*)lb;
    }
    __syncthreads();

    // ---- ssrc/sdst: exact fp32 matvec straight from global h (L1/L2-hot) ----
    if (tid < BM) {
        int r = row0 + tid;
        if (r < n) {
            float ss = 0.f, sd = 0.f;
            const float4* hp = (const float4*)(h + (size_t)r * DIM);
            #pragma unroll
            for (int q = 0; q < DIM / 4; q++) {
                float4 v = hp[q];
                const float4 a = *(const float4*)(wsv + q * 4);
                const float4 d = *(const float4*)(wdv + q * 4);
                ss = fmaf(v.x, a.x, fmaf(v.y, a.y, fmaf(v.z, a.z, fmaf(v.w, a.w, ss))));
                sd = fmaf(v.x, d.x, fmaf(v.y, d.y, fmaf(v.z, d.z, fmaf(v.w, d.w, sd))));
            }
            ssrc[r] = ss;
            sdst[r] = sd;
        }
    }

    // ---- warp MMA: warp tile 32x64; warps: m0 = (wid&3)*32, n0 = (wid>>2)*64 ----
    const int m0 = (wid & 3) * 32;
    const int n0 = (wid >> 2) * 64;
    const uint32_t sb = smem_to_u32(smem);

    // ldmatrix lane addressing (byte offsets into padded tiles)
    const int a_r = (lane & 15);               // row within 16-row A frag
    const int a_c = (lane >> 4) * 8;           // col half
    const int b_r = ((lane >> 4) << 3) + (lane & 7);
    const int b_c = ((lane >> 3) & 1) * 8;

    #pragma unroll
    for (int outm = 0; outm < 2; outm++) {
        const uint32_t bhBase = sb + (outm ? SM_UH : SM_WH) * 2;
        const uint32_t blBase = sb + (outm ? SM_UL : SM_WL) * 2;

        float acc[2][8][4];
        #pragma unroll
        for (int mf = 0; mf < 2; mf++)
            #pragma unroll
            for (int nf = 0; nf < 8; nf++)
                #pragma unroll
                for (int q = 0; q < 4; q++) acc[mf][nf][q] = 0.f;

        #pragma unroll
        for (int ks = 0; ks < 8; ks++) {
            const int k0 = ks * 16;
            uint32_t ah[2][4], al[2][4];
            #pragma unroll
            for (int mf = 0; mf < 2; mf++) {
                uint32_t off = (uint32_t)((m0 + mf * 16 + a_r) * PADS + k0 + a_c) * 2;
                ldsm4(ah[mf], sb + SM_AH * 2 + off);
                ldsm4(al[mf], sb + SM_AL * 2 + off);
            }
            uint32_t bh[4][4], bl[4][4];
            #pragma unroll
            for (int np = 0; np < 4; np++) {
                uint32_t off = (uint32_t)((n0 + np * 16 + b_r) * PADS + k0 + b_c) * 2;
                ldsm4(bh[np], bhBase + off);
                ldsm4(bl[np], blBase + off);
            }
            #pragma unroll
            for (int mf = 0; mf < 2; mf++)
                #pragma unroll
                for (int np = 0; np < 4; np++) {
                    // nf = 2*np uses regs [0..1], nf = 2*np+1 uses regs [2..3]
                    mma16816(acc[mf][2 * np + 0], ah[mf], &bh[np][0]);
                    mma16816(acc[mf][2 * np + 0], ah[mf], &bl[np][0]);
                    mma16816(acc[mf][2 * np + 0], al[mf], &bh[np][0]);
                    mma16816(acc[mf][2 * np + 1], ah[mf], &bh[np][2]);
                    mma16816(acc[mf][2 * np + 1], ah[mf], &bl[np][2]);
                    mma16816(acc[mf][2 * np + 1], al[mf], &bh[np][2]);
                }
        }

        float* dst = outm ? zi : z;
        #pragma unroll
        for (int mf = 0; mf < 2; mf++) {
            const int mA = m0 + mf * 16 + (lane >> 2);
            #pragma unroll
            for (int nf = 0; nf < 8; nf++) {
                const int c = n0 + nf * 8 + (lane & 3) * 2;
                if (row0 + mA < n)
                    *(float2*)(dst + (size_t)(row0 + mA) * DIM + c) =
                        make_float2(acc[mf][nf][0], acc[mf][nf][1]);
                if (row0 + mA + 8 < n)
                    *(float2*)(dst + (size_t)(row0 + mA + 8) * DIM + c) =
                        make_float2(acc[mf][nf][2], acc[mf][nf][3]);
            }
        }
    }
}

// ---------------- attention + aggregation (unchanged; near its L2 floor) ----------------
__global__ __launch_bounds__(256)
void attn_agg_kernel(const float* __restrict__ z, const float* __restrict__ zi,
                     const float* __restrict__ ssrc, const float* __restrict__ sdst,
                     const float* __restrict__ edge_d, const int* __restrict__ edge_src,
                     const float* __restrict__ Wv, const float* __restrict__ avec,
                     float* __restrict__ out, int n)
{
    const int node = (blockIdx.x * blockDim.x + threadIdx.x) >> 5;
    const int lane = threadIdx.x & 31;
    if (node >= n) return;

    const float c = Wv[0] * avec[2 * DIM];

    int   src = 0;
    float sc  = -1e30f;
    if (lane < DEG) {
        int e = node * DEG + lane;
        src   = edge_src[e];
        float s = ssrc[src] + sdst[node] + c * edge_d[e];
        sc = (s >= 0.f) ? s : 0.01f * s;
    }
    float m = sc;
    #pragma unroll
    for (int o = 8; o > 0; o >>= 1) m = fmaxf(m, __shfl_xor_sync(0xffffffffu, m, o));
    float ex = (lane < DEG) ? __expf(sc - m) : 0.f;
    float ssum = ex;
    #pragma unroll
    for (int o = 8; o > 0; o >>= 1) ssum += __shfl_xor_sync(0xffffffffu, ssum, o);
    float alpha = ex / ssum;

    float al[DEG];
    int   sr[DEG];
    #pragma unroll
    for (int e = 0; e < DEG; e++) {
        al[e] = __shfl_sync(0xffffffffu, alpha, e);
        sr[e] = __shfl_sync(0xffffffffu, src,   e);
    }

    float4 acc = *(const float4*)(zi + (size_t)node * DIM + lane * 4);
    #pragma unroll
    for (int e = 0; e < DEG; e++) {
        float4 v = *(const float4*)(z + (size_t)sr[e] * DIM + lane * 4);
        acc.x = fmaf(al[e], v.x, acc.x);
        acc.y = fmaf(al[e], v.y, acc.y);
        acc.z = fmaf(al[e], v.z, acc.z);
        acc.w = fmaf(al[e], v.w, acc.w);
    }
    acc.x = fmaxf(acc.x, 0.f);
    acc.y = fmaxf(acc.y, 0.f);
    acc.z = fmaxf(acc.z, 0.f);
    acc.w = fmaxf(acc.w, 0.f);
    *(float4*)(out + (size_t)node * DIM + lane * 4) = acc;
}

extern "C" void kernel_launch(void* const* d_in, const int* in_sizes, int n_in,
                              void* d_out, int out_size)
{
    const float* attr   = (const float*)d_in[0];
    const float* edge_d = (const float*)d_in[1];
    const float* Wv1    = (const float*)d_in[2];
    const float* Ww1    = (const float*)d_in[3];
    const float* Wu1    = (const float*)d_in[4];
    const float* Wa1    = (const float*)d_in[5];
    const float* Wv2    = (const float*)d_in[6];
    const float* Ww2    = (const float*)d_in[7];
    const float* Wu2    = (const float*)d_in[8];
    const float* Wa2    = (const float*)d_in[9];
    const int*   esrc   = (const int*)d_in[10];
    float*       out    = (float*)d_out;

    float *zp, *zip, *h1p, *ssp, *sdp, *wv;
    __nv_bfloat16* wb;
    cudaGetSymbolAddress((void**)&zp,  g_z);
    cudaGetSymbolAddress((void**)&zip, g_zi);
    cudaGetSymbolAddress((void**)&h1p, g_h1);
    cudaGetSymbolAddress((void**)&ssp, g_ssrc);
    cudaGetSymbolAddress((void**)&sdp, g_sdst);
    cudaGetSymbolAddress((void**)&wb,  g_wimg);
    cudaGetSymbolAddress((void**)&wv,  g_wvec);

    const __nv_bfloat16* w1h = wb + (size_t)0 * DIM * DIM;
    const __nv_bfloat16* w1l = wb + (size_t)1 * DIM * DIM;
    const __nv_bfloat16* u1h = wb + (size_t)2 * DIM * DIM;
    const __nv_bfloat16* u1l = wb + (size_t)3 * DIM * DIM;
    const __nv_bfloat16* w2h = wb + (size_t)4 * DIM * DIM;
    const __nv_bfloat16* w2l = wb + (size_t)5 * DIM * DIM;
    const __nv_bfloat16* u2h = wb + (size_t)6 * DIM * DIM;
    const __nv_bfloat16* u2l = wb + (size_t)7 * DIM * DIM;
    const float* ws1 = wv + 0 * DIM;
    const float* wd1 = wv + 1 * DIM;
    const float* ws2 = wv + 2 * DIM;
    const float* wd2 = wv + 3 * DIM;

    cudaFuncSetAttribute(gemm_mma_kernel,
                         cudaFuncAttributeMaxDynamicSharedMemorySize, SM_TOTAL_B);

    const int grid_g = (NN + BM - 1) / BM;        // 782
    const int grid_a = (NN * 32 + 255) / 256;     // 12500

    wconv_kernel<<<4, 256>>>(Ww1, Wu1, Ww2, Wu2, Wa1, Wa2);

    gemm_mma_kernel<<<grid_g, 256, SM_TOTAL_B>>>(attr, w1h, w1l, u1h, u1l, ws1, wd1,
                                                 zp, zip, ssp, sdp, NN);
    attn_agg_kernel<<<grid_a, 256>>>(zp, zip, ssp, sdp, edge_d, esrc, Wv1, Wa1, h1p, NN);

    gemm_mma_kernel<<<grid_g, 256, SM_TOTAL_B>>>(h1p, w2h, w2l, u2h, u2l, ws2, wd2,
                                                 zp, zip, ssp, sdp, NN);
    attn_agg_kernel<<<grid_a, 256>>>(zp, zip, ssp, sdp, edge_d, esrc, Wv2, Wa2, out, NN);
}

// round 5
// speedup vs baseline: 1.4630x; 1.0561x over previous
#include <cuda_runtime.h>
#include <cuda_bf16.h>
#include <cstdint>

#define NN   100000
#define DEG  16
#define DIM  128
#define BM   128
#define PADS 136                      // padded smem row stride (bf16 elems)

// ---------------- scratch (device globals: allocations are forbidden) ----------------
__device__ float g_z [(size_t)NN * DIM];
__device__ float g_zi[(size_t)NN * DIM];
__device__ float g_h1[(size_t)NN * DIM];
__device__ float g_ssrc[NN];
__device__ float g_sdst[NN];
// Pre-split weights, plain row-major bf16: [matrix: W1,U1,W2,U2][hi/lo][128*128]
__device__ __nv_bfloat16 g_wimg[4][2][DIM * DIM];
// Precomputed W^T a_src / W^T a_dst per layer: [layer][src/dst][128]
__device__ float g_wvec[2][2][DIM];

// ---------------- warp MMA helpers (base-target PTX: ldmatrix + mma.sync) ----------------
__device__ __forceinline__ uint32_t smem_to_u32(const void* p) {
    uint32_t a;
    asm("{ .reg .u64 t; cvta.to.shared.u64 t, %1; cvt.u32.u64 %0, t; }" : "=r"(a) : "l"(p));
    return a;
}
__device__ __forceinline__ void ldsm4(uint32_t* r, uint32_t addr) {
    asm volatile("ldmatrix.sync.aligned.m8n8.x4.shared.b16 {%0,%1,%2,%3}, [%4];"
                 : "=r"(r[0]), "=r"(r[1]), "=r"(r[2]), "=r"(r[3]) : "r"(addr));
}
__device__ __forceinline__ void mma16816(float* d, const uint32_t* a, const uint32_t* b) {
    asm volatile("mma.sync.aligned.m16n8k16.row.col.f32.bf16.bf16.f32 "
                 "{%0,%1,%2,%3}, {%4,%5,%6,%7}, {%8,%9}, {%0,%1,%2,%3};"
                 : "+f"(d[0]), "+f"(d[1]), "+f"(d[2]), "+f"(d[3])
                 : "r"(a[0]), "r"(a[1]), "r"(a[2]), "r"(a[3]), "r"(b[0]), "r"(b[1]));
}

// ---------------- weight conversion + score-vector precompute ----------------
__global__ void wconv_kernel(const float* __restrict__ W1, const float* __restrict__ U1,
                             const float* __restrict__ W2, const float* __restrict__ U2,
                             const float* __restrict__ Wa1, const float* __restrict__ Wa2)
{
    const int b = blockIdx.x;
    const float* src = (b == 0) ? W1 : (b == 1) ? U1 : (b == 2) ? W2 : U2;
    __nv_bfloat16* hi = g_wimg[b][0];
    __nv_bfloat16* lo = g_wimg[b][1];
    for (int c = threadIdx.x; c < DIM * DIM / 8; c += blockDim.x) {
        int row = c >> 4, cc = (c & 15) * 8;
        __align__(16) __nv_bfloat16 hb[8], lb[8];
        const float4* p = (const float4*)(src + row * DIM + cc);
        float4 v0 = p[0], v1 = p[1];
        float xs[8] = {v0.x, v0.y, v0.z, v0.w, v1.x, v1.y, v1.z, v1.w};
        #pragma unroll
        for (int j = 0; j < 8; j++) {
            __nv_bfloat16 h = __float2bfloat16(xs[j]);
            hb[j] = h;
            lb[j] = __float2bfloat16(xs[j] - __bfloat162float(h));
        }
        *(uint4*)(hi + row * DIM + cc) = *(const uint4*)hb;
        *(uint4*)(lo + row * DIM + cc) = *(const uint4*)lb;
    }
    // blocks 0/2 hold the W matrix of layer 0/1: build ws = W^T a_src, wd = W^T a_dst
    if ((b & 1) == 0) {
        const int layer = b >> 1;
        const float* Wa = layer ? Wa2 : Wa1;
        for (int k = threadIdx.x; k < DIM; k += blockDim.x) {
            float ws = 0.f, wd = 0.f;
            for (int nrow = 0; nrow < DIM; nrow++) {
                float w = src[nrow * DIM + k];
                ws = fmaf(Wa[nrow], w, ws);
                wd = fmaf(Wa[DIM + nrow], w, wd);
            }
            g_wvec[layer][0][k] = ws;
            g_wvec[layer][1][k] = wd;
        }
    }
}

// ---------------- tensor-core GEMM (legacy HMMA, bf16 3-split) ----------------
// z = h@W^T, zi = h@U^T, ssrc = h@wsv, sdst = h@wdv
// Block: 128x128 tile, 512 threads = 16 warps, warp tile 32(M)x32(N).
#define TILE (DIM * PADS)
#define SM_AH (0 * TILE)
#define SM_AL (1 * TILE)
#define SM_WH (2 * TILE)
#define SM_WL (3 * TILE)
#define SM_UH (4 * TILE)
#define SM_UL (5 * TILE)
#define SM_TOTAL_B (6 * TILE * 2)     // 208896 bytes

__global__ __launch_bounds__(512, 1)
void gemm_mma_kernel(const float* __restrict__ h,
                     const __nv_bfloat16* __restrict__ wh, const __nv_bfloat16* __restrict__ wl,
                     const __nv_bfloat16* __restrict__ uh, const __nv_bfloat16* __restrict__ ul,
                     const float* __restrict__ wsv, const float* __restrict__ wdv,
                     float* __restrict__ z, float* __restrict__ zi,
                     float* __restrict__ ssrc, float* __restrict__ sdst, int n)
{
    extern __shared__ __nv_bfloat16 smem[];
    const int tid  = threadIdx.x;
    const int lane = tid & 31;
    const int wid  = tid >> 5;
    const int row0 = blockIdx.x * BM;

    // ---- copy pre-split weights into padded smem (8-bf16 chunks) ----
    {
        const __nv_bfloat16* srcs[4] = {wh, wl, uh, ul};
        __nv_bfloat16* dsts[4] = {smem + SM_WH, smem + SM_WL, smem + SM_UH, smem + SM_UL};
        #pragma unroll
        for (int m = 0; m < 4; m++)
            for (int c = tid; c < DIM * DIM / 8; c += 512) {
                int row = c >> 4, cc = (c & 15) * 8;
                *(uint4*)(dsts[m] + row * PADS + cc) = *(const uint4*)(srcs[m] + row * DIM + cc);
            }
    }

    // ---- load + split A tile ----
    for (int c = tid; c < DIM * DIM / 8; c += 512) {
        int row = c >> 4, cc = (c & 15) * 8;
        int gr = row0 + row;
        __align__(16) __nv_bfloat16 hb[8], lb[8];
        if (gr < n) {
            const float4* p = (const float4*)(h + (size_t)gr * DIM + cc);
            float4 v0 = p[0], v1 = p[1];
            float xs[8] = {v0.x, v0.y, v0.z, v0.w, v1.x, v1.y, v1.z, v1.w};
            #pragma unroll
            for (int j = 0; j < 8; j++) {
                __nv_bfloat16 hv = __float2bfloat16(xs[j]);
                hb[j] = hv;
                lb[j] = __float2bfloat16(xs[j] - __bfloat162float(hv));
            }
        } else {
            #pragma unroll
            for (int j = 0; j < 8; j++) { hb[j] = __float2bfloat16(0.f); lb[j] = hb[j]; }
        }
        *(uint4*)(smem + SM_AH + row * PADS + cc) = *(const uint4*)hb;
        *(uint4*)(smem + SM_AL + row * PADS + cc) = *(const uint4*)lb;
    }
    __syncthreads();

    // ---- ssrc/sdst: exact fp32 matvec straight from global h (L2-hot) ----
    if (tid < BM) {
        int r = row0 + tid;
        if (r < n) {
            float ss = 0.f, sd = 0.f;
            const float4* hp = (const float4*)(h + (size_t)r * DIM);
            #pragma unroll
            for (int q = 0; q < DIM / 4; q++) {
                float4 v = hp[q];
                const float4 a = *(const float4*)(wsv + q * 4);
                const float4 d = *(const float4*)(wdv + q * 4);
                ss = fmaf(v.x, a.x, fmaf(v.y, a.y, fmaf(v.z, a.z, fmaf(v.w, a.w, ss))));
                sd = fmaf(v.x, d.x, fmaf(v.y, d.y, fmaf(v.z, d.z, fmaf(v.w, d.w, sd))));
            }
            ssrc[r] = ss;
            sdst[r] = sd;
        }
    }

    // ---- warp MMA: warp tile 32x32; m0 = (wid&3)*32, n0 = (wid>>2)*32 ----
    const int m0 = (wid & 3) * 32;
    const int n0 = (wid >> 2) * 32;
    const uint32_t sb = smem_to_u32(smem);

    // ldmatrix lane addressing (byte offsets into padded tiles)
    const int a_r = (lane & 15);
    const int a_c = (lane >> 4) * 8;
    const int b_r = ((lane >> 4) << 3) + (lane & 7);
    const int b_c = ((lane >> 3) & 1) * 8;

    #pragma unroll
    for (int outm = 0; outm < 2; outm++) {
        const uint32_t bhBase = sb + (outm ? SM_UH : SM_WH) * 2;
        const uint32_t blBase = sb + (outm ? SM_UL : SM_WL) * 2;

        float acc[2][4][4];
        #pragma unroll
        for (int mf = 0; mf < 2; mf++)
            #pragma unroll
            for (int nf = 0; nf < 4; nf++)
                #pragma unroll
                for (int q = 0; q < 4; q++) acc[mf][nf][q] = 0.f;

        #pragma unroll
        for (int ks = 0; ks < 8; ks++) {
            const int k0 = ks * 16;
            uint32_t ah[2][4], al[2][4];
            #pragma unroll
            for (int mf = 0; mf < 2; mf++) {
                uint32_t off = (uint32_t)((m0 + mf * 16 + a_r) * PADS + k0 + a_c) * 2;
                ldsm4(ah[mf], sb + SM_AH * 2 + off);
                ldsm4(al[mf], sb + SM_AL * 2 + off);
            }
            uint32_t bh[2][4], bl[2][4];
            #pragma unroll
            for (int np = 0; np < 2; np++) {
                uint32_t off = (uint32_t)((n0 + np * 16 + b_r) * PADS + k0 + b_c) * 2;
                ldsm4(bh[np], bhBase + off);
                ldsm4(bl[np], blBase + off);
            }
            #pragma unroll
            for (int mf = 0; mf < 2; mf++)
                #pragma unroll
                for (int np = 0; np < 2; np++) {
                    mma16816(acc[mf][2 * np + 0], ah[mf], &bh[np][0]);
                    mma16816(acc[mf][2 * np + 0], ah[mf], &bl[np][0]);
                    mma16816(acc[mf][2 * np + 0], al[mf], &bh[np][0]);
                    mma16816(acc[mf][2 * np + 1], ah[mf], &bh[np][2]);
                    mma16816(acc[mf][2 * np + 1], ah[mf], &bl[np][2]);
                    mma16816(acc[mf][2 * np + 1], al[mf], &bh[np][2]);
                }
        }

        float* dst = outm ? zi : z;
        #pragma unroll
        for (int mf = 0; mf < 2; mf++) {
            const int mA = m0 + mf * 16 + (lane >> 2);
            #pragma unroll
            for (int nf = 0; nf < 4; nf++) {
                const int c = n0 + nf * 8 + (lane & 3) * 2;
                if (row0 + mA < n)
                    *(float2*)(dst + (size_t)(row0 + mA) * DIM + c) =
                        make_float2(acc[mf][nf][0], acc[mf][nf][1]);
                if (row0 + mA + 8 < n)
                    *(float2*)(dst + (size_t)(row0 + mA + 8) * DIM + c) =
                        make_float2(acc[mf][nf][2], acc[mf][nf][3]);
            }
        }
    }
}

// ---------------- attention + aggregation (unchanged; near its L2 floor) ----------------
__global__ __launch_bounds__(256)
void attn_agg_kernel(const float* __restrict__ z, const float* __restrict__ zi,
                     const float* __restrict__ ssrc, const float* __restrict__ sdst,
                     const float* __restrict__ edge_d, const int* __restrict__ edge_src,
                     const float* __restrict__ Wv, const float* __restrict__ avec,
                     float* __restrict__ out, int n)
{
    const int node = (blockIdx.x * blockDim.x + threadIdx.x) >> 5;
    const int lane = threadIdx.x & 31;
    if (node >= n) return;

    const float c = Wv[0] * avec[2 * DIM];

    int   src = 0;
    float sc  = -1e30f;
    if (lane < DEG) {
        int e = node * DEG + lane;
        src   = edge_src[e];
        float s = ssrc[src] + sdst[node] + c * edge_d[e];
        sc = (s >= 0.f) ? s : 0.01f * s;
    }
    float m = sc;
    #pragma unroll
    for (int o = 8; o > 0; o >>= 1) m = fmaxf(m, __shfl_xor_sync(0xffffffffu, m, o));
    float ex = (lane < DEG) ? __expf(sc - m) : 0.f;
    float ssum = ex;
    #pragma unroll
    for (int o = 8; o > 0; o >>= 1) ssum += __shfl_xor_sync(0xffffffffu, ssum, o);
    float alpha = ex / ssum;

    float al[DEG];
    int   sr[DEG];
    #pragma unroll
    for (int e = 0; e < DEG; e++) {
        al[e] = __shfl_sync(0xffffffffu, alpha, e);
        sr[e] = __shfl_sync(0xffffffffu, src,   e);
    }

    float4 acc = *(const float4*)(zi + (size_t)node * DIM + lane * 4);
    #pragma unroll
    for (int e = 0; e < DEG; e++) {
        float4 v = *(const float4*)(z + (size_t)sr[e] * DIM + lane * 4);
        acc.x = fmaf(al[e], v.x, acc.x);
        acc.y = fmaf(al[e], v.y, acc.y);
        acc.z = fmaf(al[e], v.z, acc.z);
        acc.w = fmaf(al[e], v.w, acc.w);
    }
    acc.x = fmaxf(acc.x, 0.f);
    acc.y = fmaxf(acc.y, 0.f);
    acc.z = fmaxf(acc.z, 0.f);
    acc.w = fmaxf(acc.w, 0.f);
    *(float4*)(out + (size_t)node * DIM + lane * 4) = acc;
}

extern "C" void kernel_launch(void* const* d_in, const int* in_sizes, int n_in,
                              void* d_out, int out_size)
{
    const float* attr   = (const float*)d_in[0];
    const float* edge_d = (const float*)d_in[1];
    const float* Wv1    = (const float*)d_in[2];
    const float* Ww1    = (const float*)d_in[3];
    const float* Wu1    = (const float*)d_in[4];
    const float* Wa1    = (const float*)d_in[5];
    const float* Wv2    = (const float*)d_in[6];
    const float* Ww2    = (const float*)d_in[7];
    const float* Wu2    = (const float*)d_in[8];
    const float* Wa2    = (const float*)d_in[9];
    const int*   esrc   = (const int*)d_in[10];
    float*       out    = (float*)d_out;

    float *zp, *zip, *h1p, *ssp, *sdp, *wv;
    __nv_bfloat16* wb;
    cudaGetSymbolAddress((void**)&zp,  g_z);
    cudaGetSymbolAddress((void**)&zip, g_zi);
    cudaGetSymbolAddress((void**)&h1p, g_h1);
    cudaGetSymbolAddress((void**)&ssp, g_ssrc);
    cudaGetSymbolAddress((void**)&sdp, g_sdst);
    cudaGetSymbolAddress((void**)&wb,  g_wimg);
    cudaGetSymbolAddress((void**)&wv,  g_wvec);

    const __nv_bfloat16* w1h = wb + (size_t)0 * DIM * DIM;
    const __nv_bfloat16* w1l = wb + (size_t)1 * DIM * DIM;
    const __nv_bfloat16* u1h = wb + (size_t)2 * DIM * DIM;
    const __nv_bfloat16* u1l = wb + (size_t)3 * DIM * DIM;
    const __nv_bfloat16* w2h = wb + (size_t)4 * DIM * DIM;
    const __nv_bfloat16* w2l = wb + (size_t)5 * DIM * DIM;
    const __nv_bfloat16* u2h = wb + (size_t)6 * DIM * DIM;
    const __nv_bfloat16* u2l = wb + (size_t)7 * DIM * DIM;
    const float* ws1 = wv + 0 * DIM;
    const float* wd1 = wv + 1 * DIM;
    const float* ws2 = wv + 2 * DIM;
    const float* wd2 = wv + 3 * DIM;

    cudaFuncSetAttribute(gemm_mma_kernel,
                         cudaFuncAttributeMaxDynamicSharedMemorySize, SM_TOTAL_B);

    const int grid_g = (NN + BM - 1) / BM;        // 782
    const int grid_a = (NN * 32 + 255) / 256;     // 12500

    wconv_kernel<<<4, 256>>>(Ww1, Wu1, Ww2, Wu2, Wa1, Wa2);

    gemm_mma_kernel<<<grid_g, 512, SM_TOTAL_B>>>(attr, w1h, w1l, u1h, u1l, ws1, wd1,
                                                 zp, zip, ssp, sdp, NN);
    attn_agg_kernel<<<grid_a, 256>>>(zp, zip, ssp, sdp, edge_d, esrc, Wv1, Wa1, h1p, NN);

    gemm_mma_kernel<<<grid_g, 512, SM_TOTAL_B>>>(h1p, w2h, w2l, u2h, u2l, ws2, wd2,
                                                 zp, zip, ssp, sdp, NN);
    attn_agg_kernel<<<grid_a, 256>>>(zp, zip, ssp, sdp, edge_d, esrc, Wv2, Wa2, out, NN);
}

// round 9
// speedup vs baseline: 1.6607x; 1.1351x over previous
#include <cuda_runtime.h>
#include <cuda_bf16.h>
#include <cstdint>

#define NN   100000
#define DEG  16
#define DIM  128
#define PADS 136                      // padded smem row stride (bf16 elems)
#define TM   64                       // rows per persistent-loop tile
#define NT   ((NN + TM - 1) / TM)     // 1563 tiles
#define GRIDP 148                     // persistent CTAs (1/SM)

// ---------------- scratch (device globals: allocations are forbidden) ----------------
__device__ float g_z [(size_t)NN * DIM];
__device__ float g_zi[(size_t)NN * DIM];
__device__ float g_h1[(size_t)NN * DIM];
__device__ float g_ssrc[NN];
__device__ float g_sdst[NN];
// Pre-split weights, plain row-major bf16: [matrix: W1,U1,W2,U2][hi/lo][128*128]
__device__ __nv_bfloat16 g_wimg[4][2][DIM * DIM];
// Precomputed W^T a_src / W^T a_dst per layer: [layer][src/dst][128]
__device__ float g_wvec[2][2][DIM];

// ---------------- warp MMA helpers (base-target PTX: ldmatrix + mma.sync) ----------------
__device__ __forceinline__ uint32_t smem_to_u32(const void* p) {
    uint32_t a;
    asm("{ .reg .u64 t; cvta.to.shared.u64 t, %1; cvt.u32.u64 %0, t; }" : "=r"(a) : "l"(p));
    return a;
}
__device__ __forceinline__ void ldsm4(uint32_t* r, uint32_t addr) {
    asm volatile("ldmatrix.sync.aligned.m8n8.x4.shared.b16 {%0,%1,%2,%3}, [%4];"
                 : "=r"(r[0]), "=r"(r[1]), "=r"(r[2]), "=r"(r[3]) : "r"(addr));
}
__device__ __forceinline__ void mma16816(float* d, const uint32_t* a, const uint32_t* b) {
    asm volatile("mma.sync.aligned.m16n8k16.row.col.f32.bf16.bf16.f32 "
                 "{%0,%1,%2,%3}, {%4,%5,%6,%7}, {%8,%9}, {%0,%1,%2,%3};"
                 : "+f"(d[0]), "+f"(d[1]), "+f"(d[2]), "+f"(d[3])
                 : "r"(a[0]), "r"(a[1]), "r"(a[2]), "r"(a[3]), "r"(b[0]), "r"(b[1]));
}

// ---------------- weight conversion + score-vector precompute ----------------
__global__ void wconv_kernel(const float* __restrict__ W1, const float* __restrict__ U1,
                             const float* __restrict__ W2, const float* __restrict__ U2,
                             const float* __restrict__ Wa1, const float* __restrict__ Wa2)
{
    const int b = blockIdx.x;
    const float* src = (b == 0) ? W1 : (b == 1) ? U1 : (b == 2) ? W2 : U2;
    __nv_bfloat16* hi = g_wimg[b][0];
    __nv_bfloat16* lo = g_wimg[b][1];
    for (int c = threadIdx.x; c < DIM * DIM / 8; c += blockDim.x) {
        int row = c >> 4, cc = (c & 15) * 8;
        __align__(16) __nv_bfloat16 hb[8], lb[8];
        const float4* p = (const float4*)(src + row * DIM + cc);
        float4 v0 = p[0], v1 = p[1];
        float xs[8] = {v0.x, v0.y, v0.z, v0.w, v1.x, v1.y, v1.z, v1.w};
        #pragma unroll
        for (int j = 0; j < 8; j++) {
            __nv_bfloat16 h = __float2bfloat16(xs[j]);
            hb[j] = h;
            lb[j] = __float2bfloat16(xs[j] - __bfloat162float(h));
        }
        *(uint4*)(hi + row * DIM + cc) = *(const uint4*)hb;
        *(uint4*)(lo + row * DIM + cc) = *(const uint4*)lb;
    }
    if ((b & 1) == 0) {
        const int layer = b >> 1;
        const float* Wa = layer ? Wa2 : Wa1;
        for (int k = threadIdx.x; k < DIM; k += blockDim.x) {
            float ws = 0.f, wd = 0.f;
            for (int nrow = 0; nrow < DIM; nrow++) {
                float w = src[nrow * DIM + k];
                ws = fmaf(Wa[nrow], w, ws);
                wd = fmaf(Wa[DIM + nrow], w, wd);
            }
            g_wvec[layer][0][k] = ws;
            g_wvec[layer][1][k] = wd;
        }
    }
}

// ---------------- persistent tensor-core GEMM (legacy HMMA, bf16 3-split) ----------------
// smem layout (bf16 elems)
#define TILE128 (DIM * PADS)
#define TILE64  (TM * PADS)
#define SM_WH   (0 * TILE128)
#define SM_WL   (1 * TILE128)
#define SM_UH   (2 * TILE128)
#define SM_UL   (3 * TILE128)
#define SM_AOFF (4 * TILE128)
#define SM_TOTAL_B ((4 * TILE128 + 4 * TILE64) * 2)   // 208896 bytes

__global__ __launch_bounds__(512, 1)
void gemm_persist_kernel(const float* __restrict__ h,
                     const __nv_bfloat16* __restrict__ wh, const __nv_bfloat16* __restrict__ wl,
                     const __nv_bfloat16* __restrict__ uh, const __nv_bfloat16* __restrict__ ul,
                     const float* __restrict__ wsv, const float* __restrict__ wdv,
                     float* __restrict__ z, float* __restrict__ zi,
                     float* __restrict__ ssrc, float* __restrict__ sdst, int n)
{
    extern __shared__ __nv_bfloat16 smem[];
    const int tid  = threadIdx.x;
    const int lane = tid & 31;
    const int wid  = tid >> 5;
    const uint32_t sb = smem_to_u32(smem);

    // ---- load weights ONCE per persistent CTA ----
    {
        const __nv_bfloat16* srcs[4] = {wh, wl, uh, ul};
        __nv_bfloat16* dsts[4] = {smem + SM_WH, smem + SM_WL, smem + SM_UH, smem + SM_UL};
        #pragma unroll
        for (int m = 0; m < 4; m++)
            for (int c = tid; c < DIM * DIM / 8; c += 512) {
                int row = c >> 4, cc = (c & 15) * 8;
                *(uint4*)(dsts[m] + row * PADS + cc) = *(const uint4*)(srcs[m] + row * DIM + cc);
            }
    }

    // per-thread A-tile element mapping: 64 rows x 32 float4 = 2048 float4, 4 per thread
    int arow[4], aq[4];
    #pragma unroll
    for (int i = 0; i < 4; i++) { int idx = tid + i * 512; arow[i] = idx >> 5; aq[i] = idx & 31; }

    // warp tiling: m0 in {0,16,32,48}, n0 in {0,32,64,96}
    const int m0 = (wid & 3) * 16;
    const int n0 = (wid >> 2) * 32;
    const int a_r = (lane & 15);
    const int a_c = (lane >> 4) * 8;
    const int b_r = ((lane >> 4) << 3) + (lane & 7);
    const int b_c = ((lane >> 3) & 1) * 8;

    // preload first tile into registers
    int t = blockIdx.x;
    float4 pre[4];
    if (t < NT) {
        #pragma unroll
        for (int i = 0; i < 4; i++) {
            int gr = t * TM + arow[i];
            pre[i] = (gr < n) ? *(const float4*)(h + (size_t)gr * DIM + aq[i] * 4)
                              : make_float4(0.f, 0.f, 0.f, 0.f);
        }
    }

    int p = 0;
    for (; t < NT; t += GRIDP) {
        const int row0 = t * TM;

        // ---- convert preloaded regs -> A buf p (hi/lo) ----
        {
            __nv_bfloat16* ahB = smem + SM_AOFF + (p * 2 + 0) * TILE64;
            __nv_bfloat16* alB = smem + SM_AOFF + (p * 2 + 1) * TILE64;
            #pragma unroll
            for (int i = 0; i < 4; i++) {
                __align__(8) __nv_bfloat16 hb[4], lb[4];
                float xs[4] = {pre[i].x, pre[i].y, pre[i].z, pre[i].w};
                #pragma unroll
                for (int j = 0; j < 4; j++) {
                    __nv_bfloat16 hv = __float2bfloat16(xs[j]);
                    hb[j] = hv;
                    lb[j] = __float2bfloat16(xs[j] - __bfloat162float(hv));
                }
                int eo = arow[i] * PADS + aq[i] * 4;
                *(uint2*)(ahB + eo) = *(const uint2*)hb;
                *(uint2*)(alB + eo) = *(const uint2*)lb;
            }
        }
        __syncthreads();

        // ---- preload NEXT tile (LDG latency hides under MMA) ----
        {
            int tn = t + GRIDP;
            if (tn < NT) {
                #pragma unroll
                for (int i = 0; i < 4; i++) {
                    int gr = tn * TM + arow[i];
                    pre[i] = (gr < n) ? *(const float4*)(h + (size_t)gr * DIM + aq[i] * 4)
                                      : make_float4(0.f, 0.f, 0.f, 0.f);
                }
            }
        }

        // ---- ssrc/sdst exact fp32 matvec (rows are L1/L2-hot) ----
        if (tid < TM) {
            int r = row0 + tid;
            if (r < n) {
                float ss = 0.f, sd = 0.f;
                const float4* hp = (const float4*)(h + (size_t)r * DIM);
                #pragma unroll
                for (int q = 0; q < DIM / 4; q++) {
                    float4 v = hp[q];
                    const float4 a = *(const float4*)(wsv + q * 4);
                    const float4 d = *(const float4*)(wdv + q * 4);
                    ss = fmaf(v.x, a.x, fmaf(v.y, a.y, fmaf(v.z, a.z, fmaf(v.w, a.w, ss))));
                    sd = fmaf(v.x, d.x, fmaf(v.y, d.y, fmaf(v.z, d.z, fmaf(v.w, d.w, sd))));
                }
                ssrc[r] = ss;
                sdst[r] = sd;
            }
        }

        // ---- MMA: both outputs in one K-pass (A frags shared) ----
        float acc[2][4][4];
        #pragma unroll
        for (int m = 0; m < 2; m++)
            #pragma unroll
            for (int nf = 0; nf < 4; nf++)
                #pragma unroll
                for (int q = 0; q < 4; q++) acc[m][nf][q] = 0.f;

        const uint32_t aHi = sb + (uint32_t)(SM_AOFF + (p * 2 + 0) * TILE64) * 2;
        const uint32_t aLo = sb + (uint32_t)(SM_AOFF + (p * 2 + 1) * TILE64) * 2;

        #pragma unroll
        for (int ks = 0; ks < 8; ks++) {
            const int k0 = ks * 16;
            const uint32_t aoff = (uint32_t)((m0 + a_r) * PADS + k0 + a_c) * 2;
            uint32_t ah[4], al[4];
            ldsm4(ah, aHi + aoff);
            ldsm4(al, aLo + aoff);

            uint32_t bwh[2][4], bwl[2][4], buh[2][4], bul[2][4];
            #pragma unroll
            for (int np = 0; np < 2; np++) {
                const uint32_t boff = (uint32_t)((n0 + np * 16 + b_r) * PADS + k0 + b_c) * 2;
                ldsm4(bwh[np], sb + (uint32_t)SM_WH * 2 + boff);
                ldsm4(bwl[np], sb + (uint32_t)SM_WL * 2 + boff);
                ldsm4(buh[np], sb + (uint32_t)SM_UH * 2 + boff);
                ldsm4(bul[np], sb + (uint32_t)SM_UL * 2 + boff);
            }
            #pragma unroll
            for (int np = 0; np < 2; np++) {
                mma16816(acc[0][2 * np + 0], ah, &bwh[np][0]);
                mma16816(acc[0][2 * np + 0], ah, &bwl[np][0]);
                mma16816(acc[0][2 * np + 0], al, &bwh[np][0]);
                mma16816(acc[0][2 * np + 1], ah, &bwh[np][2]);
                mma16816(acc[0][2 * np + 1], ah, &bwl[np][2]);
                mma16816(acc[0][2 * np + 1], al, &bwh[np][2]);
                mma16816(acc[1][2 * np + 0], ah, &buh[np][0]);
                mma16816(acc[1][2 * np + 0], ah, &bul[np][0]);
                mma16816(acc[1][2 * np + 0], al, &buh[np][0]);
                mma16816(acc[1][2 * np + 1], ah, &buh[np][2]);
                mma16816(acc[1][2 * np + 1], ah, &bul[np][2]);
                mma16816(acc[1][2 * np + 1], al, &buh[np][2]);
            }
        }

        // ---- epilogue: direct STG ----
        {
            const int mA = row0 + m0 + (lane >> 2);
            #pragma unroll
            for (int m = 0; m < 2; m++) {
                float* dst = m ? zi : z;
                #pragma unroll
                for (int nf = 0; nf < 4; nf++) {
                    const int c = n0 + nf * 8 + (lane & 3) * 2;
                    if (mA < n)
                        *(float2*)(dst + (size_t)mA * DIM + c) =
                            make_float2(acc[m][nf][0], acc[m][nf][1]);
                    if (mA + 8 < n)
                        *(float2*)(dst + (size_t)(mA + 8) * DIM + c) =
                            make_float2(acc[m][nf][2], acc[m][nf][3]);
                }
            }
        }
        p ^= 1;
    }
}

// ---------------- attention + aggregation (unchanged; near its L2 floor) ----------------
__global__ __launch_bounds__(256)
void attn_agg_kernel(const float* __restrict__ z, const float* __restrict__ zi,
                     const float* __restrict__ ssrc, const float* __restrict__ sdst,
                     const float* __restrict__ edge_d, const int* __restrict__ edge_src,
                     const float* __restrict__ Wv, const float* __restrict__ avec,
                     float* __restrict__ out, int n)
{
    const int node = (blockIdx.x * blockDim.x + threadIdx.x) >> 5;
    const int lane = threadIdx.x & 31;
    if (node >= n) return;

    const float c = Wv[0] * avec[2 * DIM];

    int   src = 0;
    float sc  = -1e30f;
    if (lane < DEG) {
        int e = node * DEG + lane;
        src   = edge_src[e];
        float s = ssrc[src] + sdst[node] + c * edge_d[e];
        sc = (s >= 0.f) ? s : 0.01f * s;
    }
    float m = sc;
    #pragma unroll
    for (int o = 8; o > 0; o >>= 1) m = fmaxf(m, __shfl_xor_sync(0xffffffffu, m, o));
    float ex = (lane < DEG) ? __expf(sc - m) : 0.f;
    float ssum = ex;
    #pragma unroll
    for (int o = 8; o > 0; o >>= 1) ssum += __shfl_xor_sync(0xffffffffu, ssum, o);
    float alpha = ex / ssum;

    float al[DEG];
    int   sr[DEG];
    #pragma unroll
    for (int e = 0; e < DEG; e++) {
        al[e] = __shfl_sync(0xffffffffu, alpha, e);
        sr[e] = __shfl_sync(0xffffffffu, src,   e);
    }

    float4 acc = *(const float4*)(zi + (size_t)node * DIM + lane * 4);
    #pragma unroll
    for (int e = 0; e < DEG; e++) {
        float4 v = *(const float4*)(z + (size_t)sr[e] * DIM + lane * 4);
        acc.x = fmaf(al[e], v.x, acc.x);
        acc.y = fmaf(al[e], v.y, acc.y);
        acc.z = fmaf(al[e], v.z, acc.z);
        acc.w = fmaf(al[e], v.w, acc.w);
    }
    acc.x = fmaxf(acc.x, 0.f);
    acc.y = fmaxf(acc.y, 0.f);
    acc.z = fmaxf(acc.z, 0.f);
    acc.w = fmaxf(acc.w, 0.f);
    *(float4*)(out + (size_t)node * DIM + lane * 4) = acc;
}

extern "C" void kernel_launch(void* const* d_in, const int* in_sizes, int n_in,
                              void* d_out, int out_size)
{
    const float* attr   = (const float*)d_in[0];
    const float* edge_d = (const float*)d_in[1];
    const float* Wv1    = (const float*)d_in[2];
    const float* Ww1    = (const float*)d_in[3];
    const float* Wu1    = (const float*)d_in[4];
    const float* Wa1    = (const float*)d_in[5];
    const float* Wv2    = (const float*)d_in[6];
    const float* Ww2    = (const float*)d_in[7];
    const float* Wu2    = (const float*)d_in[8];
    const float* Wa2    = (const float*)d_in[9];
    const int*   esrc   = (const int*)d_in[10];
    float*       out    = (float*)d_out;

    float *zp, *zip, *h1p, *ssp, *sdp, *wv;
    __nv_bfloat16* wb;
    cudaGetSymbolAddress((void**)&zp,  g_z);
    cudaGetSymbolAddress((void**)&zip, g_zi);
    cudaGetSymbolAddress((void**)&h1p, g_h1);
    cudaGetSymbolAddress((void**)&ssp, g_ssrc);
    cudaGetSymbolAddress((void**)&sdp, g_sdst);
    cudaGetSymbolAddress((void**)&wb,  g_wimg);
    cudaGetSymbolAddress((void**)&wv,  g_wvec);

    const __nv_bfloat16* w1h = wb + (size_t)0 * DIM * DIM;
    const __nv_bfloat16* w1l = wb + (size_t)1 * DIM * DIM;
    const __nv_bfloat16* u1h = wb + (size_t)2 * DIM * DIM;
    const __nv_bfloat16* u1l = wb + (size_t)3 * DIM * DIM;
    const __nv_bfloat16* w2h = wb + (size_t)4 * DIM * DIM;
    const __nv_bfloat16* w2l = wb + (size_t)5 * DIM * DIM;
    const __nv_bfloat16* u2h = wb + (size_t)6 * DIM * DIM;
    const __nv_bfloat16* u2l = wb + (size_t)7 * DIM * DIM;
    const float* ws1 = wv + 0 * DIM;
    const float* wd1 = wv + 1 * DIM;
    const float* ws2 = wv + 2 * DIM;
    const float* wd2 = wv + 3 * DIM;

    cudaFuncSetAttribute(gemm_persist_kernel,
                         cudaFuncAttributeMaxDynamicSharedMemorySize, SM_TOTAL_B);

    const int grid_a = (NN * 32 + 255) / 256;     // 12500

    wconv_kernel<<<4, 256>>>(Ww1, Wu1, Ww2, Wu2, Wa1, Wa2);

    gemm_persist_kernel<<<GRIDP, 512, SM_TOTAL_B>>>(attr, w1h, w1l, u1h, u1l, ws1, wd1,
                                                    zp, zip, ssp, sdp, NN);
    attn_agg_kernel<<<grid_a, 256>>>(zp, zip, ssp, sdp, edge_d, esrc, Wv1, Wa1, h1p, NN);

    gemm_persist_kernel<<<GRIDP, 512, SM_TOTAL_B>>>(h1p, w2h, w2l, u2h, u2l, ws2, wd2,
                                                    zp, zip, ssp, sdp, NN);
    attn_agg_kernel<<<grid_a, 256>>>(zp, zip, ssp, sdp, edge_d, esrc, Wv2, Wa2, out, NN);
}

// round 10
// speedup vs baseline: 1.8608x; 1.1205x over previous
#include <cuda_runtime.h>
#include <cuda_bf16.h>
#include <cstdint>

#define NN   100000
#define DEG  16
#define DIM  128
#define PADS 136                      // padded smem row stride (bf16 elems)
#define TM   96                       // rows per persistent-loop tile
#define NT   ((NN + TM - 1) / TM)     // 1042 tiles
#define GRIDP 148                     // persistent CTAs (1/SM)

// ---------------- scratch (device globals: allocations are forbidden) ----------------
__device__ float g_z [(size_t)NN * DIM];
__device__ float g_zi[(size_t)NN * DIM];
__device__ float g_h1[(size_t)NN * DIM];
__device__ float g_ssrc[NN];
__device__ float g_sdst[NN];
// Pre-split weights, plain row-major bf16: [matrix: W1,U1,W2,U2][hi/lo][128*128]
__device__ __nv_bfloat16 g_wimg[4][2][DIM * DIM];

// ---------------- warp MMA helpers (base-target PTX: ldmatrix + mma.sync) ----------------
__device__ __forceinline__ uint32_t smem_to_u32(const void* p) {
    uint32_t a;
    asm("{ .reg .u64 t; cvta.to.shared.u64 t, %1; cvt.u32.u64 %0, t; }" : "=r"(a) : "l"(p));
    return a;
}
__device__ __forceinline__ void ldsm4(uint32_t* r, uint32_t addr) {
    asm volatile("ldmatrix.sync.aligned.m8n8.x4.shared.b16 {%0,%1,%2,%3}, [%4];"
                 : "=r"(r[0]), "=r"(r[1]), "=r"(r[2]), "=r"(r[3]) : "r"(addr));
}
__device__ __forceinline__ void mma16816(float* d, const uint32_t* a, const uint32_t* b) {
    asm volatile("mma.sync.aligned.m16n8k16.row.col.f32.bf16.bf16.f32 "
                 "{%0,%1,%2,%3}, {%4,%5,%6,%7}, {%8,%9}, {%0,%1,%2,%3};"
                 : "+f"(d[0]), "+f"(d[1]), "+f"(d[2]), "+f"(d[3])
                 : "r"(a[0]), "r"(a[1]), "r"(a[2]), "r"(a[3]), "r"(b[0]), "r"(b[1]));
}

// ---------------- weight conversion (hi/lo bf16 split) ----------------
__global__ void wconv_kernel(const float* __restrict__ W1, const float* __restrict__ U1,
                             const float* __restrict__ W2, const float* __restrict__ U2)
{
    const int b = blockIdx.x;
    const float* src = (b == 0) ? W1 : (b == 1) ? U1 : (b == 2) ? W2 : U2;
    __nv_bfloat16* hi = g_wimg[b][0];
    __nv_bfloat16* lo = g_wimg[b][1];
    for (int c = threadIdx.x; c < DIM * DIM / 8; c += blockDim.x) {
        int row = c >> 4, cc = (c & 15) * 8;
        __align__(16) __nv_bfloat16 hb[8], lb[8];
        const float4* p = (const float4*)(src + row * DIM + cc);
        float4 v0 = p[0], v1 = p[1];
        float xs[8] = {v0.x, v0.y, v0.z, v0.w, v1.x, v1.y, v1.z, v1.w};
        #pragma unroll
        for (int j = 0; j < 8; j++) {
            __nv_bfloat16 h = __float2bfloat16(xs[j]);
            hb[j] = h;
            lb[j] = __float2bfloat16(xs[j] - __bfloat162float(h));
        }
        *(uint4*)(hi + row * DIM + cc) = *(const uint4*)hb;
        *(uint4*)(lo + row * DIM + cc) = *(const uint4*)lb;
    }
}

// ---------------- persistent tensor-core GEMM (legacy HMMA, bf16 3-split) ----------------
// smem layout (bf16 elems), scores smem (float) appended
#define TILE128 (DIM * PADS)
#define TILE96  (TM * PADS)
#define SM_WH   (0 * TILE128)
#define SM_WL   (1 * TILE128)
#define SM_UH   (2 * TILE128)
#define SM_UL   (3 * TILE128)
#define SM_AH   (4 * TILE128)
#define SM_AL   (4 * TILE128 + TILE96)
#define SM_BF16_ELEMS (4 * TILE128 + 2 * TILE96)
#define SM_TOTAL_B (SM_BF16_ELEMS * 2 + 2 * TM * 4 * 4)   // 191488 + 3072 = 194560

__global__ __launch_bounds__(384, 1)
void gemm_persist_kernel(const float* __restrict__ h,
                     const __nv_bfloat16* __restrict__ wh, const __nv_bfloat16* __restrict__ wl,
                     const __nv_bfloat16* __restrict__ uh, const __nv_bfloat16* __restrict__ ul,
                     const float* __restrict__ avec,
                     float* __restrict__ z, float* __restrict__ zi,
                     float* __restrict__ ssrc, float* __restrict__ sdst, int n)
{
    extern __shared__ __nv_bfloat16 smem[];
    float* sred = (float*)(smem + SM_BF16_ELEMS);     // [2][96][4]
    const int tid  = threadIdx.x;
    const int lane = tid & 31;
    const int wid  = tid >> 5;
    const uint32_t sb = smem_to_u32(smem);

    // ---- load weights ONCE per persistent CTA ----
    {
        const __nv_bfloat16* srcs[4] = {wh, wl, uh, ul};
        __nv_bfloat16* dsts[4] = {smem + SM_WH, smem + SM_WL, smem + SM_UH, smem + SM_UL};
        #pragma unroll
        for (int m = 0; m < 4; m++)
            for (int c = tid; c < DIM * DIM / 8; c += 384) {
                int row = c >> 4, cc = (c & 15) * 8;
                *(uint4*)(dsts[m] + row * PADS + cc) = *(const uint4*)(srcs[m] + row * DIM + cc);
            }
    }

    // per-thread A-tile mapping: 96 rows x 32 float4 = 3072 float4, 8 per thread
    int arow[8], aq[8];
    #pragma unroll
    for (int i = 0; i < 8; i++) { int idx = tid + i * 384; arow[i] = idx >> 5; aq[i] = idx & 31; }

    // warp tiling: 3 M-warps x 4 N-warps, warp tile 32x32
    const int mw = wid % 3, nw = wid / 3;
    const int m0 = mw * 32;
    const int n0 = nw * 32;
    const int a_r = (lane & 15);
    const int a_c = (lane >> 4) * 8;
    const int b_r = ((lane >> 4) << 3) + (lane & 7);
    const int b_c = ((lane >> 3) & 1) * 8;

    // preload first tile into registers
    int t = blockIdx.x;
    float4 pre[8];
    if (t < NT) {
        #pragma unroll
        for (int i = 0; i < 8; i++) {
            int gr = t * TM + arow[i];
            pre[i] = (gr < n) ? *(const float4*)(h + (size_t)gr * DIM + aq[i] * 4)
                              : make_float4(0.f, 0.f, 0.f, 0.f);
        }
    }

    for (; t < NT; t += GRIDP) {
        const int row0 = t * TM;

        // ---- convert preloaded regs -> A smem (hi/lo) ----
        #pragma unroll
        for (int i = 0; i < 8; i++) {
            __align__(8) __nv_bfloat16 hb[4], lb[4];
            float xs[4] = {pre[i].x, pre[i].y, pre[i].z, pre[i].w};
            #pragma unroll
            for (int j = 0; j < 4; j++) {
                __nv_bfloat16 hv = __float2bfloat16(xs[j]);
                hb[j] = hv;
                lb[j] = __float2bfloat16(xs[j] - __bfloat162float(hv));
            }
            int eo = arow[i] * PADS + aq[i] * 4;
            *(uint2*)(smem + SM_AH + eo) = *(const uint2*)hb;
            *(uint2*)(smem + SM_AL + eo) = *(const uint2*)lb;
        }
        __syncthreads();

        // ---- preload NEXT tile (LDG latency hides under MMA) ----
        {
            int tn = t + GRIDP;
            if (tn < NT) {
                #pragma unroll
                for (int i = 0; i < 8; i++) {
                    int gr = tn * TM + arow[i];
                    pre[i] = (gr < n) ? *(const float4*)(h + (size_t)gr * DIM + aq[i] * 4)
                                      : make_float4(0.f, 0.f, 0.f, 0.f);
                }
            }
        }

        // ---- MMA: warp tile 32x32, both outputs, one K-pass ----
        float acc[2][2][4][4];
        #pragma unroll
        for (int m = 0; m < 2; m++)
            #pragma unroll
            for (int mf = 0; mf < 2; mf++)
                #pragma unroll
                for (int nf = 0; nf < 4; nf++)
                    #pragma unroll
                    for (int q = 0; q < 4; q++) acc[m][mf][nf][q] = 0.f;

        const uint32_t aHi = sb + (uint32_t)SM_AH * 2;
        const uint32_t aLo = sb + (uint32_t)SM_AL * 2;

        #pragma unroll
        for (int ks = 0; ks < 8; ks++) {
            const int k0 = ks * 16;
            uint32_t ah[2][4], al[2][4];
            #pragma unroll
            for (int mf = 0; mf < 2; mf++) {
                const uint32_t aoff = (uint32_t)((m0 + mf * 16 + a_r) * PADS + k0 + a_c) * 2;
                ldsm4(ah[mf], aHi + aoff);
                ldsm4(al[mf], aLo + aoff);
            }
            #pragma unroll
            for (int np = 0; np < 2; np++) {
                const uint32_t boff = (uint32_t)((n0 + np * 16 + b_r) * PADS + k0 + b_c) * 2;
                uint32_t bwh[4], bwl[4], buh[4], bul[4];
                ldsm4(bwh, sb + (uint32_t)SM_WH * 2 + boff);
                ldsm4(bwl, sb + (uint32_t)SM_WL * 2 + boff);
                ldsm4(buh, sb + (uint32_t)SM_UH * 2 + boff);
                ldsm4(bul, sb + (uint32_t)SM_UL * 2 + boff);
                #pragma unroll
                for (int mf = 0; mf < 2; mf++) {
                    mma16816(acc[0][mf][2 * np + 0], ah[mf], &bwh[0]);
                    mma16816(acc[0][mf][2 * np + 0], ah[mf], &bwl[0]);
                    mma16816(acc[0][mf][2 * np + 0], al[mf], &bwh[0]);
                    mma16816(acc[0][mf][2 * np + 1], ah[mf], &bwh[2]);
                    mma16816(acc[0][mf][2 * np + 1], ah[mf], &bwl[2]);
                    mma16816(acc[0][mf][2 * np + 1], al[mf], &bwh[2]);
                    mma16816(acc[1][mf][2 * np + 0], ah[mf], &buh[0]);
                    mma16816(acc[1][mf][2 * np + 0], ah[mf], &bul[0]);
                    mma16816(acc[1][mf][2 * np + 0], al[mf], &buh[0]);
                    mma16816(acc[1][mf][2 * np + 1], ah[mf], &buh[2]);
                    mma16816(acc[1][mf][2 * np + 1], ah[mf], &bul[2]);
                    mma16816(acc[1][mf][2 * np + 1], al[mf], &buh[2]);
                }
            }
        }

        // ---- epilogue: direct STG of z, zi ----
        #pragma unroll
        for (int mf = 0; mf < 2; mf++) {
            const int mA = row0 + m0 + mf * 16 + (lane >> 2);
            #pragma unroll
            for (int m = 0; m < 2; m++) {
                float* dst = m ? zi : z;
                #pragma unroll
                for (int nf = 0; nf < 4; nf++) {
                    const int c = n0 + nf * 8 + (lane & 3) * 2;
                    if (mA < n)
                        *(float2*)(dst + (size_t)mA * DIM + c) =
                            make_float2(acc[m][mf][nf][0], acc[m][mf][nf][1]);
                    if (mA + 8 < n)
                        *(float2*)(dst + (size_t)(mA + 8) * DIM + c) =
                            make_float2(acc[m][mf][nf][2], acc[m][mf][nf][3]);
                }
            }
        }

        // ---- scores from z accumulators: ss = z . a_src, sd = z . a_dst ----
        {
            float asv[4][2], adv[4][2];
            #pragma unroll
            for (int nf = 0; nf < 4; nf++) {
                const int c = n0 + nf * 8 + (lane & 3) * 2;
                asv[nf][0] = avec[c];       asv[nf][1] = avec[c + 1];
                adv[nf][0] = avec[DIM + c]; adv[nf][1] = avec[DIM + c + 1];
            }
            #pragma unroll
            for (int mf = 0; mf < 2; mf++) {
                float s0 = 0.f, s1 = 0.f, d0 = 0.f, d1 = 0.f;
                #pragma unroll
                for (int nf = 0; nf < 4; nf++) {
                    s0 += acc[0][mf][nf][0] * asv[nf][0] + acc[0][mf][nf][1] * asv[nf][1];
                    s1 += acc[0][mf][nf][2] * asv[nf][0] + acc[0][mf][nf][3] * asv[nf][1];
                    d0 += acc[0][mf][nf][0] * adv[nf][0] + acc[0][mf][nf][1] * adv[nf][1];
                    d1 += acc[0][mf][nf][2] * adv[nf][0] + acc[0][mf][nf][3] * adv[nf][1];
                }
                #pragma unroll
                for (int o = 1; o <= 2; o <<= 1) {
                    s0 += __shfl_xor_sync(0xffffffffu, s0, o);
                    s1 += __shfl_xor_sync(0xffffffffu, s1, o);
                    d0 += __shfl_xor_sync(0xffffffffu, d0, o);
                    d1 += __shfl_xor_sync(0xffffffffu, d1, o);
                }
                if ((lane & 3) == 0) {
                    const int lr = m0 + mf * 16 + (lane >> 2);
                    sred[lr * 4 + nw]              = s0;
                    sred[(lr + 8) * 4 + nw]        = s1;
                    sred[TM * 4 + lr * 4 + nw]       = d0;
                    sred[TM * 4 + (lr + 8) * 4 + nw] = d1;
                }
            }
        }
        __syncthreads();   // protects A smem overwrite AND sred

        if (tid < TM) {
            const int r = row0 + tid;
            if (r < n) {
                ssrc[r] = sred[tid * 4 + 0] + sred[tid * 4 + 1]
                        + sred[tid * 4 + 2] + sred[tid * 4 + 3];
                sdst[r] = sred[TM * 4 + tid * 4 + 0] + sred[TM * 4 + tid * 4 + 1]
                        + sred[TM * 4 + tid * 4 + 2] + sred[TM * 4 + tid * 4 + 3];
            }
        }
    }
}

// ---------------- attention + aggregation (unchanged; near its L2 floor) ----------------
__global__ __launch_bounds__(256)
void attn_agg_kernel(const float* __restrict__ z, const float* __restrict__ zi,
                     const float* __restrict__ ssrc, const float* __restrict__ sdst,
                     const float* __restrict__ edge_d, const int* __restrict__ edge_src,
                     const float* __restrict__ Wv, const float* __restrict__ avec,
                     float* __restrict__ out, int n)
{
    const int node = (blockIdx.x * blockDim.x + threadIdx.x) >> 5;
    const int lane = threadIdx.x & 31;
    if (node >= n) return;

    const float c = Wv[0] * avec[2 * DIM];

    int   src = 0;
    float sc  = -1e30f;
    if (lane < DEG) {
        int e = node * DEG + lane;
        src   = edge_src[e];
        float s = ssrc[src] + sdst[node] + c * edge_d[e];
        sc = (s >= 0.f) ? s : 0.01f * s;
    }
    float m = sc;
    #pragma unroll
    for (int o = 8; o > 0; o >>= 1) m = fmaxf(m, __shfl_xor_sync(0xffffffffu, m, o));
    float ex = (lane < DEG) ? __expf(sc - m) : 0.f;
    float ssum = ex;
    #pragma unroll
    for (int o = 8; o > 0; o >>= 1) ssum += __shfl_xor_sync(0xffffffffu, ssum, o);
    float alpha = ex / ssum;

    float al[DEG];
    int   sr[DEG];
    #pragma unroll
    for (int e = 0; e < DEG; e++) {
        al[e] = __shfl_sync(0xffffffffu, alpha, e);
        sr[e] = __shfl_sync(0xffffffffu, src,   e);
    }

    float4 acc = *(const float4*)(zi + (size_t)node * DIM + lane * 4);
    #pragma unroll
    for (int e = 0; e < DEG; e++) {
        float4 v = *(const float4*)(z + (size_t)sr[e] * DIM + lane * 4);
        acc.x = fmaf(al[e], v.x, acc.x);
        acc.y = fmaf(al[e], v.y, acc.y);
        acc.z = fmaf(al[e], v.z, acc.z);
        acc.w = fmaf(al[e], v.w, acc.w);
    }
    acc.x = fmaxf(acc.x, 0.f);
    acc.y = fmaxf(acc.y, 0.f);
    acc.z = fmaxf(acc.z, 0.f);
    acc.w = fmaxf(acc.w, 0.f);
    *(float4*)(out + (size_t)node * DIM + lane * 4) = acc;
}

extern "C" void kernel_launch(void* const* d_in, const int* in_sizes, int n_in,
                              void* d_out, int out_size)
{
    const float* attr   = (const float*)d_in[0];
    const float* edge_d = (const float*)d_in[1];
    const float* Wv1    = (const float*)d_in[2];
    const float* Ww1    = (const float*)d_in[3];
    const float* Wu1    = (const float*)d_in[4];
    const float* Wa1    = (const float*)d_in[5];
    const float* Wv2    = (const float*)d_in[6];
    const float* Ww2    = (const float*)d_in[7];
    const float* Wu2    = (const float*)d_in[8];
    const float* Wa2    = (const float*)d_in[9];
    const int*   esrc   = (const int*)d_in[10];
    float*       out    = (float*)d_out;

    float *zp, *zip, *h1p, *ssp, *sdp;
    __nv_bfloat16* wb;
    cudaGetSymbolAddress((void**)&zp,  g_z);
    cudaGetSymbolAddress((void**)&zip, g_zi);
    cudaGetSymbolAddress((void**)&h1p, g_h1);
    cudaGetSymbolAddress((void**)&ssp, g_ssrc);
    cudaGetSymbolAddress((void**)&sdp, g_sdst);
    cudaGetSymbolAddress((void**)&wb,  g_wimg);

    const __nv_bfloat16* w1h = wb + (size_t)0 * DIM * DIM;
    const __nv_bfloat16* w1l = wb + (size_t)1 * DIM * DIM;
    const __nv_bfloat16* u1h = wb + (size_t)2 * DIM * DIM;
    const __nv_bfloat16* u1l = wb + (size_t)3 * DIM * DIM;
    const __nv_bfloat16* w2h = wb + (size_t)4 * DIM * DIM;
    const __nv_bfloat16* w2l = wb + (size_t)5 * DIM * DIM;
    const __nv_bfloat16* u2h = wb + (size_t)6 * DIM * DIM;
    const __nv_bfloat16* u2l = wb + (size_t)7 * DIM * DIM;

    cudaFuncSetAttribute(gemm_persist_kernel,
                         cudaFuncAttributeMaxDynamicSharedMemorySize, SM_TOTAL_B);

    const int grid_a = (NN * 32 + 255) / 256;     // 12500

    wconv_kernel<<<4, 256>>>(Ww1, Wu1, Ww2, Wu2);

    gemm_persist_kernel<<<GRIDP, 384, SM_TOTAL_B>>>(attr, w1h, w1l, u1h, u1l, Wa1,
                                                    zp, zip, ssp, sdp, NN);
    attn_agg_kernel<<<grid_a, 256>>>(zp, zip, ssp, sdp, edge_d, esrc, Wv1, Wa1, h1p, NN);

    gemm_persist_kernel<<<GRIDP, 384, SM_TOTAL_B>>>(h1p, w2h, w2l, u2h, u2l, Wa2,
                                                    zp, zip, ssp, sdp, NN);
    attn_agg_kernel<<<grid_a, 256>>>(zp, zip, ssp, sdp, edge_d, esrc, Wv2, Wa2, out, NN);
}

// round 11
// speedup vs baseline: 1.9391x; 1.0421x over previous
#include <cuda_runtime.h>
#include <cuda_bf16.h>
#include <cstdint>

#define NN   100000
#define DEG  16
#define DIM  128
#define PADS 136                      // padded smem row stride (bf16 elems)
#define TM   64                       // rows per persistent-loop tile
#define NT   ((NN + TM - 1) / TM)     // 1563 tiles
#define GRIDP 148                     // persistent CTAs per output type

// ---------------- scratch (device globals: allocations are forbidden) ----------------
__device__ float g_z [(size_t)NN * DIM];
__device__ float g_zi[(size_t)NN * DIM];
__device__ float g_h1[(size_t)NN * DIM];
__device__ float g_ssrc[NN];
__device__ float g_sdst[NN];
// Pre-split weights, plain row-major bf16: [matrix: W1,U1,W2,U2][hi/lo][128*128]
__device__ __nv_bfloat16 g_wimg[4][2][DIM * DIM];

// ---------------- warp MMA helpers (base-target PTX: ldmatrix + mma.sync) ----------------
__device__ __forceinline__ uint32_t smem_to_u32(const void* p) {
    uint32_t a;
    asm("{ .reg .u64 t; cvta.to.shared.u64 t, %1; cvt.u32.u64 %0, t; }" : "=r"(a) : "l"(p));
    return a;
}
__device__ __forceinline__ void ldsm4(uint32_t* r, uint32_t addr) {
    asm volatile("ldmatrix.sync.aligned.m8n8.x4.shared.b16 {%0,%1,%2,%3}, [%4];"
                 : "=r"(r[0]), "=r"(r[1]), "=r"(r[2]), "=r"(r[3]) : "r"(addr));
}
__device__ __forceinline__ void mma16816(float* d, const uint32_t* a, const uint32_t* b) {
    asm volatile("mma.sync.aligned.m16n8k16.row.col.f32.bf16.bf16.f32 "
                 "{%0,%1,%2,%3}, {%4,%5,%6,%7}, {%8,%9}, {%0,%1,%2,%3};"
                 : "+f"(d[0]), "+f"(d[1]), "+f"(d[2]), "+f"(d[3])
                 : "r"(a[0]), "r"(a[1]), "r"(a[2]), "r"(a[3]), "r"(b[0]), "r"(b[1]));
}

// ---------------- weight conversion (hi/lo bf16 split) ----------------
__global__ void wconv_kernel(const float* __restrict__ W1, const float* __restrict__ U1,
                             const float* __restrict__ W2, const float* __restrict__ U2)
{
    const int b = blockIdx.x;
    const float* src = (b == 0) ? W1 : (b == 1) ? U1 : (b == 2) ? W2 : U2;
    __nv_bfloat16* hi = g_wimg[b][0];
    __nv_bfloat16* lo = g_wimg[b][1];
    for (int c = threadIdx.x; c < DIM * DIM / 8; c += blockDim.x) {
        int row = c >> 4, cc = (c & 15) * 8;
        __align__(16) __nv_bfloat16 hb[8], lb[8];
        const float4* p = (const float4*)(src + row * DIM + cc);
        float4 v0 = p[0], v1 = p[1];
        float xs[8] = {v0.x, v0.y, v0.z, v0.w, v1.x, v1.y, v1.z, v1.w};
        #pragma unroll
        for (int j = 0; j < 8; j++) {
            __nv_bfloat16 h = __float2bfloat16(xs[j]);
            hb[j] = h;
            lb[j] = __float2bfloat16(xs[j] - __bfloat162float(h));
        }
        *(uint4*)(hi + row * DIM + cc) = *(const uint4*)hb;
        *(uint4*)(lo + row * DIM + cc) = *(const uint4*)lb;
    }
}

// ---------------- persistent split-output tensor-core GEMM ----------------
// CTA type z  (bid <  148): z  = h@W^T + scores (ssrc/sdst from z accumulators)
// CTA type zi (bid >= 148): zi = h@U^T
// 2 CTAs/SM co-resident: one CTA's barriers/epilogue overlap the other's MMAs.
#define TILE128 (DIM * PADS)          // 17408 elems (one 128x128 weight split)
#define TILE64  (TM * PADS)           // 8704 elems
#define SM_BH   0
#define SM_BL   (1 * TILE128)
#define SM_AH   (2 * TILE128)
#define SM_AL   (2 * TILE128 + TILE64)
#define SM_BF16_ELEMS (2 * TILE128 + 2 * TILE64)
#define SM_TOTAL_B (SM_BF16_ELEMS * 2 + 2 * TM * 4 * 4)   // 104448 + 2048 = 106496

__global__ __launch_bounds__(256, 2)
void gemm_split_kernel(const float* __restrict__ h,
                     const __nv_bfloat16* __restrict__ wh, const __nv_bfloat16* __restrict__ wl,
                     const __nv_bfloat16* __restrict__ uh, const __nv_bfloat16* __restrict__ ul,
                     const float* __restrict__ avec,
                     float* __restrict__ z, float* __restrict__ zi,
                     float* __restrict__ ssrc, float* __restrict__ sdst, int n)
{
    extern __shared__ __nv_bfloat16 smem[];
    float* sred = (float*)(smem + SM_BF16_ELEMS);     // [2][64][4] (z-CTAs only)
    const int tid  = threadIdx.x;
    const int lane = tid & 31;
    const int wid  = tid >> 5;
    const uint32_t sb = smem_to_u32(smem);

    const bool isU = (blockIdx.x >= GRIDP);
    const int  t0  = blockIdx.x - (isU ? GRIDP : 0);

    // ---- load this CTA's weight pair ONCE ----
    {
        const __nv_bfloat16* bhsrc = isU ? uh : wh;
        const __nv_bfloat16* blsrc = isU ? ul : wl;
        for (int c = tid; c < DIM * DIM / 8; c += 256) {
            int row = c >> 4, cc = (c & 15) * 8;
            *(uint4*)(smem + SM_BH + row * PADS + cc) = *(const uint4*)(bhsrc + row * DIM + cc);
            *(uint4*)(smem + SM_BL + row * PADS + cc) = *(const uint4*)(blsrc + row * DIM + cc);
        }
    }

    // per-thread A-tile mapping: 64 rows x 32 float4 = 2048 float4, 8 per thread
    int arow[8], aq[8];
    #pragma unroll
    for (int i = 0; i < 8; i++) { int idx = tid + i * 256; arow[i] = idx >> 5; aq[i] = idx & 31; }

    // warp tiling: 2 M-warps x 4 N-warps, warp tile 32x32
    const int m0 = (wid & 1) * 32;
    const int nw = wid >> 1;
    const int n0 = nw * 32;
    const int a_r = (lane & 15);
    const int a_c = (lane >> 4) * 8;
    const int b_r = ((lane >> 4) << 3) + (lane & 7);
    const int b_c = ((lane >> 3) & 1) * 8;

    float* dst = isU ? zi : z;

    // preload first tile into registers
    int t = t0;
    float4 pre[8];
    if (t < NT) {
        #pragma unroll
        for (int i = 0; i < 8; i++) {
            int gr = t * TM + arow[i];
            pre[i] = (gr < n) ? *(const float4*)(h + (size_t)gr * DIM + aq[i] * 4)
                              : make_float4(0.f, 0.f, 0.f, 0.f);
        }
    }

    for (; t < NT; t += GRIDP) {
        const int row0 = t * TM;

        // ---- convert preloaded regs -> A smem (hi/lo) ----
        #pragma unroll
        for (int i = 0; i < 8; i++) {
            __align__(8) __nv_bfloat16 hb[4], lb[4];
            float xs[4] = {pre[i].x, pre[i].y, pre[i].z, pre[i].w};
            #pragma unroll
            for (int j = 0; j < 4; j++) {
                __nv_bfloat16 hv = __float2bfloat16(xs[j]);
                hb[j] = hv;
                lb[j] = __float2bfloat16(xs[j] - __bfloat162float(hv));
            }
            int eo = arow[i] * PADS + aq[i] * 4;
            *(uint2*)(smem + SM_AH + eo) = *(const uint2*)hb;
            *(uint2*)(smem + SM_AL + eo) = *(const uint2*)lb;
        }
        __syncthreads();

        // ---- preload NEXT tile (LDG latency hides under MMA / other CTA) ----
        {
            int tn = t + GRIDP;
            if (tn < NT) {
                #pragma unroll
                for (int i = 0; i < 8; i++) {
                    int gr = tn * TM + arow[i];
                    pre[i] = (gr < n) ? *(const float4*)(h + (size_t)gr * DIM + aq[i] * 4)
                                      : make_float4(0.f, 0.f, 0.f, 0.f);
                }
            }
        }

        // ---- MMA: warp tile 32x32, single output, 3-split ----
        float acc[2][4][4];
        #pragma unroll
        for (int mf = 0; mf < 2; mf++)
            #pragma unroll
            for (int nf = 0; nf < 4; nf++)
                #pragma unroll
                for (int q = 0; q < 4; q++) acc[mf][nf][q] = 0.f;

        #pragma unroll
        for (int ks = 0; ks < 8; ks++) {
            const int k0 = ks * 16;
            uint32_t ah[2][4], al[2][4];
            #pragma unroll
            for (int mf = 0; mf < 2; mf++) {
                const uint32_t aoff = (uint32_t)((m0 + mf * 16 + a_r) * PADS + k0 + a_c) * 2;
                ldsm4(ah[mf], sb + (uint32_t)SM_AH * 2 + aoff);
                ldsm4(al[mf], sb + (uint32_t)SM_AL * 2 + aoff);
            }
            #pragma unroll
            for (int np = 0; np < 2; np++) {
                const uint32_t boff = (uint32_t)((n0 + np * 16 + b_r) * PADS + k0 + b_c) * 2;
                uint32_t bh[4], bl[4];
                ldsm4(bh, sb + (uint32_t)SM_BH * 2 + boff);
                ldsm4(bl, sb + (uint32_t)SM_BL * 2 + boff);
                #pragma unroll
                for (int mf = 0; mf < 2; mf++) {
                    mma16816(acc[mf][2 * np + 0], ah[mf], &bh[0]);
                    mma16816(acc[mf][2 * np + 0], ah[mf], &bl[0]);
                    mma16816(acc[mf][2 * np + 0], al[mf], &bh[0]);
                    mma16816(acc[mf][2 * np + 1], ah[mf], &bh[2]);
                    mma16816(acc[mf][2 * np + 1], ah[mf], &bl[2]);
                    mma16816(acc[mf][2 * np + 1], al[mf], &bh[2]);
                }
            }
        }

        // ---- epilogue: direct STG ----
        #pragma unroll
        for (int mf = 0; mf < 2; mf++) {
            const int mA = row0 + m0 + mf * 16 + (lane >> 2);
            #pragma unroll
            for (int nf = 0; nf < 4; nf++) {
                const int c = n0 + nf * 8 + (lane & 3) * 2;
                if (mA < n)
                    *(float2*)(dst + (size_t)mA * DIM + c) =
                        make_float2(acc[mf][nf][0], acc[mf][nf][1]);
                if (mA + 8 < n)
                    *(float2*)(dst + (size_t)(mA + 8) * DIM + c) =
                        make_float2(acc[mf][nf][2], acc[mf][nf][3]);
            }
        }

        // ---- scores from z accumulators (z-CTAs only) ----
        if (!isU) {
            float asv[4][2], adv[4][2];
            #pragma unroll
            for (int nf = 0; nf < 4; nf++) {
                const int c = n0 + nf * 8 + (lane & 3) * 2;
                asv[nf][0] = avec[c];       asv[nf][1] = avec[c + 1];
                adv[nf][0] = avec[DIM + c]; adv[nf][1] = avec[DIM + c + 1];
            }
            #pragma unroll
            for (int mf = 0; mf < 2; mf++) {
                float s0 = 0.f, s1 = 0.f, d0 = 0.f, d1 = 0.f;
                #pragma unroll
                for (int nf = 0; nf < 4; nf++) {
                    s0 += acc[mf][nf][0] * asv[nf][0] + acc[mf][nf][1] * asv[nf][1];
                    s1 += acc[mf][nf][2] * asv[nf][0] + acc[mf][nf][3] * asv[nf][1];
                    d0 += acc[mf][nf][0] * adv[nf][0] + acc[mf][nf][1] * adv[nf][1];
                    d1 += acc[mf][nf][2] * adv[nf][0] + acc[mf][nf][3] * adv[nf][1];
                }
                #pragma unroll
                for (int o = 1; o <= 2; o <<= 1) {
                    s0 += __shfl_xor_sync(0xffffffffu, s0, o);
                    s1 += __shfl_xor_sync(0xffffffffu, s1, o);
                    d0 += __shfl_xor_sync(0xffffffffu, d0, o);
                    d1 += __shfl_xor_sync(0xffffffffu, d1, o);
                }
                if ((lane & 3) == 0) {
                    const int lr = m0 + mf * 16 + (lane >> 2);
                    sred[lr * 4 + nw]              = s0;
                    sred[(lr + 8) * 4 + nw]        = s1;
                    sred[TM * 4 + lr * 4 + nw]       = d0;
                    sred[TM * 4 + (lr + 8) * 4 + nw] = d1;
                }
            }
        }
        __syncthreads();   // protects A smem overwrite AND sred

        if (!isU && tid < TM) {
            const int r = row0 + tid;
            if (r < n) {
                ssrc[r] = sred[tid * 4 + 0] + sred[tid * 4 + 1]
                        + sred[tid * 4 + 2] + sred[tid * 4 + 3];
                sdst[r] = sred[TM * 4 + tid * 4 + 0] + sred[TM * 4 + tid * 4 + 1]
                        + sred[TM * 4 + tid * 4 + 2] + sred[TM * 4 + tid * 4 + 3];
            }
        }
    }
}

// ---------------- attention + aggregation (unchanged; near its L2 floor) ----------------
__global__ __launch_bounds__(256)
void attn_agg_kernel(const float* __restrict__ z, const float* __restrict__ zi,
                     const float* __restrict__ ssrc, const float* __restrict__ sdst,
                     const float* __restrict__ edge_d, const int* __restrict__ edge_src,
                     const float* __restrict__ Wv, const float* __restrict__ avec,
                     float* __restrict__ out, int n)
{
    const int node = (blockIdx.x * blockDim.x + threadIdx.x) >> 5;
    const int lane = threadIdx.x & 31;
    if (node >= n) return;

    const float c = Wv[0] * avec[2 * DIM];

    int   src = 0;
    float sc  = -1e30f;
    if (lane < DEG) {
        int e = node * DEG + lane;
        src   = edge_src[e];
        float s = ssrc[src] + sdst[node] + c * edge_d[e];
        sc = (s >= 0.f) ? s : 0.01f * s;
    }
    float m = sc;
    #pragma unroll
    for (int o = 8; o > 0; o >>= 1) m = fmaxf(m, __shfl_xor_sync(0xffffffffu, m, o));
    float ex = (lane < DEG) ? __expf(sc - m) : 0.f;
    float ssum = ex;
    #pragma unroll
    for (int o = 8; o > 0; o >>= 1) ssum += __shfl_xor_sync(0xffffffffu, ssum, o);
    float alpha = ex / ssum;

    float al[DEG];
    int   sr[DEG];
    #pragma unroll
    for (int e = 0; e < DEG; e++) {
        al[e] = __shfl_sync(0xffffffffu, alpha, e);
        sr[e] = __shfl_sync(0xffffffffu, src,   e);
    }

    float4 acc = *(const float4*)(zi + (size_t)node * DIM + lane * 4);
    #pragma unroll
    for (int e = 0; e < DEG; e++) {
        float4 v = *(const float4*)(z + (size_t)sr[e] * DIM + lane * 4);
        acc.x = fmaf(al[e], v.x, acc.x);
        acc.y = fmaf(al[e], v.y, acc.y);
        acc.z = fmaf(al[e], v.z, acc.z);
        acc.w = fmaf(al[e], v.w, acc.w);
    }
    acc.x = fmaxf(acc.x, 0.f);
    acc.y = fmaxf(acc.y, 0.f);
    acc.z = fmaxf(acc.z, 0.f);
    acc.w = fmaxf(acc.w, 0.f);
    *(float4*)(out + (size_t)node * DIM + lane * 4) = acc;
}

extern "C" void kernel_launch(void* const* d_in, const int* in_sizes, int n_in,
                              void* d_out, int out_size)
{
    const float* attr   = (const float*)d_in[0];
    const float* edge_d = (const float*)d_in[1];
    const float* Wv1    = (const float*)d_in[2];
    const float* Ww1    = (const float*)d_in[3];
    const float* Wu1    = (const float*)d_in[4];
    const float* Wa1    = (const float*)d_in[5];
    const float* Wv2    = (const float*)d_in[6];
    const float* Ww2    = (const float*)d_in[7];
    const float* Wu2    = (const float*)d_in[8];
    const float* Wa2    = (const float*)d_in[9];
    const int*   esrc   = (const int*)d_in[10];
    float*       out    = (float*)d_out;

    float *zp, *zip, *h1p, *ssp, *sdp;
    __nv_bfloat16* wb;
    cudaGetSymbolAddress((void**)&zp,  g_z);
    cudaGetSymbolAddress((void**)&zip, g_zi);
    cudaGetSymbolAddress((void**)&h1p, g_h1);
    cudaGetSymbolAddress((void**)&ssp, g_ssrc);
    cudaGetSymbolAddress((void**)&sdp, g_sdst);
    cudaGetSymbolAddress((void**)&wb,  g_wimg);

    const __nv_bfloat16* w1h = wb + (size_t)0 * DIM * DIM;
    const __nv_bfloat16* w1l = wb + (size_t)1 * DIM * DIM;
    const __nv_bfloat16* u1h = wb + (size_t)2 * DIM * DIM;
    const __nv_bfloat16* u1l = wb + (size_t)3 * DIM * DIM;
    const __nv_bfloat16* w2h = wb + (size_t)4 * DIM * DIM;
    const __nv_bfloat16* w2l = wb + (size_t)5 * DIM * DIM;
    const __nv_bfloat16* u2h = wb + (size_t)6 * DIM * DIM;
    const __nv_bfloat16* u2l = wb + (size_t)7 * DIM * DIM;

    cudaFuncSetAttribute(gemm_split_kernel,
                         cudaFuncAttributeMaxDynamicSharedMemorySize, SM_TOTAL_B);

    const int grid_a = (NN * 32 + 255) / 256;     // 12500

    wconv_kernel<<<4, 256>>>(Ww1, Wu1, Ww2, Wu2);

    gemm_split_kernel<<<2 * GRIDP, 256, SM_TOTAL_B>>>(attr, w1h, w1l, u1h, u1l, Wa1,
                                                      zp, zip, ssp, sdp, NN);
    attn_agg_kernel<<<grid_a, 256>>>(zp, zip, ssp, sdp, edge_d, esrc, Wv1, Wa1, h1p, NN);

    gemm_split_kernel<<<2 * GRIDP, 256, SM_TOTAL_B>>>(h1p, w2h, w2l, u2h, u2l, Wa2,
                                                      zp, zip, ssp, sdp, NN);
    attn_agg_kernel<<<grid_a, 256>>>(zp, zip, ssp, sdp, edge_d, esrc, Wv2, Wa2, out, NN);
}

// round 12
// speedup vs baseline: 2.1763x; 1.1224x over previous
#include <cuda_runtime.h>
#include <cuda_bf16.h>
#include <cuda_fp16.h>
#include <cstdint>

#define NN   100000
#define DEG  16
#define DIM  128
#define PADS 136                      // padded smem row stride (bf16 elems)
#define TM   64                       // rows per persistent-loop tile
#define NT   ((NN + TM - 1) / TM)     // 1563 tiles
#define GRIDP 148                     // persistent CTAs per output type

// ---------------- scratch (device globals: allocations are forbidden) ----------------
__device__ __half g_z [(size_t)NN * DIM];   // fp16 interchange: only consumed by attn gather
__device__ __half g_zi[(size_t)NN * DIM];
__device__ float g_h1[(size_t)NN * DIM];
__device__ float g_ssrc[NN];
__device__ float g_sdst[NN];
// Pre-split weights, plain row-major bf16: [matrix: W1,U1,W2,U2][hi/lo][128*128]
__device__ __nv_bfloat16 g_wimg[4][2][DIM * DIM];

// ---------------- warp MMA helpers (base-target PTX: ldmatrix + mma.sync) ----------------
__device__ __forceinline__ uint32_t smem_to_u32(const void* p) {
    uint32_t a;
    asm("{ .reg .u64 t; cvta.to.shared.u64 t, %1; cvt.u32.u64 %0, t; }" : "=r"(a) : "l"(p));
    return a;
}
__device__ __forceinline__ void ldsm4(uint32_t* r, uint32_t addr) {
    asm volatile("ldmatrix.sync.aligned.m8n8.x4.shared.b16 {%0,%1,%2,%3}, [%4];"
                 : "=r"(r[0]), "=r"(r[1]), "=r"(r[2]), "=r"(r[3]) : "r"(addr));
}
__device__ __forceinline__ void mma16816(float* d, const uint32_t* a, const uint32_t* b) {
    asm volatile("mma.sync.aligned.m16n8k16.row.col.f32.bf16.bf16.f32 "
                 "{%0,%1,%2,%3}, {%4,%5,%6,%7}, {%8,%9}, {%0,%1,%2,%3};"
                 : "+f"(d[0]), "+f"(d[1]), "+f"(d[2]), "+f"(d[3])
                 : "r"(a[0]), "r"(a[1]), "r"(a[2]), "r"(a[3]), "r"(b[0]), "r"(b[1]));
}

// ---------------- weight conversion (hi/lo bf16 split) ----------------
__global__ void wconv_kernel(const float* __restrict__ W1, const float* __restrict__ U1,
                             const float* __restrict__ W2, const float* __restrict__ U2)
{
    const int b = blockIdx.x;
    const float* src = (b == 0) ? W1 : (b == 1) ? U1 : (b == 2) ? W2 : U2;
    __nv_bfloat16* hi = g_wimg[b][0];
    __nv_bfloat16* lo = g_wimg[b][1];
    for (int c = threadIdx.x; c < DIM * DIM / 8; c += blockDim.x) {
        int row = c >> 4, cc = (c & 15) * 8;
        __align__(16) __nv_bfloat16 hb[8], lb[8];
        const float4* p = (const float4*)(src + row * DIM + cc);
        float4 v0 = p[0], v1 = p[1];
        float xs[8] = {v0.x, v0.y, v0.z, v0.w, v1.x, v1.y, v1.z, v1.w};
        #pragma unroll
        for (int j = 0; j < 8; j++) {
            __nv_bfloat16 h = __float2bfloat16(xs[j]);
            hb[j] = h;
            lb[j] = __float2bfloat16(xs[j] - __bfloat162float(h));
        }
        *(uint4*)(hi + row * DIM + cc) = *(const uint4*)hb;
        *(uint4*)(lo + row * DIM + cc) = *(const uint4*)lb;
    }
}

// ---------------- persistent split-output tensor-core GEMM ----------------
// CTA type z  (bid <  148): z  = h@W^T (fp16 out) + scores (fp32, from accumulators)
// CTA type zi (bid >= 148): zi = h@U^T (fp16 out)
#define TILE128 (DIM * PADS)
#define TILE64  (TM * PADS)
#define SM_BH   0
#define SM_BL   (1 * TILE128)
#define SM_AH   (2 * TILE128)
#define SM_AL   (2 * TILE128 + TILE64)
#define SM_BF16_ELEMS (2 * TILE128 + 2 * TILE64)
#define SM_TOTAL_B (SM_BF16_ELEMS * 2 + 2 * TM * 4 * 4)   // 104448 + 2048 = 106496

__global__ __launch_bounds__(256, 2)
void gemm_split_kernel(const float* __restrict__ h,
                     const __nv_bfloat16* __restrict__ wh, const __nv_bfloat16* __restrict__ wl,
                     const __nv_bfloat16* __restrict__ uh, const __nv_bfloat16* __restrict__ ul,
                     const float* __restrict__ avec,
                     __half* __restrict__ z, __half* __restrict__ zi,
                     float* __restrict__ ssrc, float* __restrict__ sdst, int n)
{
    extern __shared__ __nv_bfloat16 smem[];
    float* sred = (float*)(smem + SM_BF16_ELEMS);     // [2][64][4] (z-CTAs only)
    const int tid  = threadIdx.x;
    const int lane = tid & 31;
    const int wid  = tid >> 5;
    const uint32_t sb = smem_to_u32(smem);

    const bool isU = (blockIdx.x >= GRIDP);
    const int  t0  = blockIdx.x - (isU ? GRIDP : 0);

    // ---- load this CTA's weight pair ONCE ----
    {
        const __nv_bfloat16* bhsrc = isU ? uh : wh;
        const __nv_bfloat16* blsrc = isU ? ul : wl;
        for (int c = tid; c < DIM * DIM / 8; c += 256) {
            int row = c >> 4, cc = (c & 15) * 8;
            *(uint4*)(smem + SM_BH + row * PADS + cc) = *(const uint4*)(bhsrc + row * DIM + cc);
            *(uint4*)(smem + SM_BL + row * PADS + cc) = *(const uint4*)(blsrc + row * DIM + cc);
        }
    }

    // per-thread A-tile mapping: 64 rows x 32 float4 = 2048 float4, 8 per thread
    int arow[8], aq[8];
    #pragma unroll
    for (int i = 0; i < 8; i++) { int idx = tid + i * 256; arow[i] = idx >> 5; aq[i] = idx & 31; }

    // warp tiling: 2 M-warps x 4 N-warps, warp tile 32x32
    const int m0 = (wid & 1) * 32;
    const int nw = wid >> 1;
    const int n0 = nw * 32;
    const int a_r = (lane & 15);
    const int a_c = (lane >> 4) * 8;
    const int b_r = ((lane >> 4) << 3) + (lane & 7);
    const int b_c = ((lane >> 3) & 1) * 8;

    __half* dst = isU ? zi : z;

    // preload first tile into registers
    int t = t0;
    float4 pre[8];
    if (t < NT) {
        #pragma unroll
        for (int i = 0; i < 8; i++) {
            int gr = t * TM + arow[i];
            pre[i] = (gr < n) ? *(const float4*)(h + (size_t)gr * DIM + aq[i] * 4)
                              : make_float4(0.f, 0.f, 0.f, 0.f);
        }
    }

    for (; t < NT; t += GRIDP) {
        const int row0 = t * TM;

        // ---- convert preloaded regs -> A smem (hi/lo) ----
        #pragma unroll
        for (int i = 0; i < 8; i++) {
            __align__(8) __nv_bfloat16 hb[4], lb[4];
            float xs[4] = {pre[i].x, pre[i].y, pre[i].z, pre[i].w};
            #pragma unroll
            for (int j = 0; j < 4; j++) {
                __nv_bfloat16 hv = __float2bfloat16(xs[j]);
                hb[j] = hv;
                lb[j] = __float2bfloat16(xs[j] - __bfloat162float(hv));
            }
            int eo = arow[i] * PADS + aq[i] * 4;
            *(uint2*)(smem + SM_AH + eo) = *(const uint2*)hb;
            *(uint2*)(smem + SM_AL + eo) = *(const uint2*)lb;
        }
        __syncthreads();

        // ---- preload NEXT tile (LDG latency hides under MMA / other CTA) ----
        {
            int tn = t + GRIDP;
            if (tn < NT) {
                #pragma unroll
                for (int i = 0; i < 8; i++) {
                    int gr = tn * TM + arow[i];
                    pre[i] = (gr < n) ? *(const float4*)(h + (size_t)gr * DIM + aq[i] * 4)
                                      : make_float4(0.f, 0.f, 0.f, 0.f);
                }
            }
        }

        // ---- MMA: warp tile 32x32, single output, 3-split ----
        float acc[2][4][4];
        #pragma unroll
        for (int mf = 0; mf < 2; mf++)
            #pragma unroll
            for (int nf = 0; nf < 4; nf++)
                #pragma unroll
                for (int q = 0; q < 4; q++) acc[mf][nf][q] = 0.f;

        #pragma unroll
        for (int ks = 0; ks < 8; ks++) {
            const int k0 = ks * 16;
            uint32_t ah[2][4], al[2][4];
            #pragma unroll
            for (int mf = 0; mf < 2; mf++) {
                const uint32_t aoff = (uint32_t)((m0 + mf * 16 + a_r) * PADS + k0 + a_c) * 2;
                ldsm4(ah[mf], sb + (uint32_t)SM_AH * 2 + aoff);
                ldsm4(al[mf], sb + (uint32_t)SM_AL * 2 + aoff);
            }
            #pragma unroll
            for (int np = 0; np < 2; np++) {
                const uint32_t boff = (uint32_t)((n0 + np * 16 + b_r) * PADS + k0 + b_c) * 2;
                uint32_t bh[4], bl[4];
                ldsm4(bh, sb + (uint32_t)SM_BH * 2 + boff);
                ldsm4(bl, sb + (uint32_t)SM_BL * 2 + boff);
                #pragma unroll
                for (int mf = 0; mf < 2; mf++) {
                    mma16816(acc[mf][2 * np + 0], ah[mf], &bh[0]);
                    mma16816(acc[mf][2 * np + 0], ah[mf], &bl[0]);
                    mma16816(acc[mf][2 * np + 0], al[mf], &bh[0]);
                    mma16816(acc[mf][2 * np + 1], ah[mf], &bh[2]);
                    mma16816(acc[mf][2 * np + 1], ah[mf], &bl[2]);
                    mma16816(acc[mf][2 * np + 1], al[mf], &bh[2]);
                }
            }
        }

        // ---- epilogue: fp16 STG ----
        #pragma unroll
        for (int mf = 0; mf < 2; mf++) {
            const int mA = row0 + m0 + mf * 16 + (lane >> 2);
            #pragma unroll
            for (int nf = 0; nf < 4; nf++) {
                const int c = n0 + nf * 8 + (lane & 3) * 2;
                if (mA < n)
                    *(__half2*)(dst + (size_t)mA * DIM + c) =
                        __floats2half2_rn(acc[mf][nf][0], acc[mf][nf][1]);
                if (mA + 8 < n)
                    *(__half2*)(dst + (size_t)(mA + 8) * DIM + c) =
                        __floats2half2_rn(acc[mf][nf][2], acc[mf][nf][3]);
            }
        }

        // ---- scores from z accumulators (z-CTAs only, exact fp32) ----
        if (!isU) {
            float asv[4][2], adv[4][2];
            #pragma unroll
            for (int nf = 0; nf < 4; nf++) {
                const int c = n0 + nf * 8 + (lane & 3) * 2;
                asv[nf][0] = avec[c];       asv[nf][1] = avec[c + 1];
                adv[nf][0] = avec[DIM + c]; adv[nf][1] = avec[DIM + c + 1];
            }
            #pragma unroll
            for (int mf = 0; mf < 2; mf++) {
                float s0 = 0.f, s1 = 0.f, d0 = 0.f, d1 = 0.f;
                #pragma unroll
                for (int nf = 0; nf < 4; nf++) {
                    s0 += acc[mf][nf][0] * asv[nf][0] + acc[mf][nf][1] * asv[nf][1];
                    s1 += acc[mf][nf][2] * asv[nf][0] + acc[mf][nf][3] * asv[nf][1];
                    d0 += acc[mf][nf][0] * adv[nf][0] + acc[mf][nf][1] * adv[nf][1];
                    d1 += acc[mf][nf][2] * adv[nf][0] + acc[mf][nf][3] * adv[nf][1];
                }
                #pragma unroll
                for (int o = 1; o <= 2; o <<= 1) {
                    s0 += __shfl_xor_sync(0xffffffffu, s0, o);
                    s1 += __shfl_xor_sync(0xffffffffu, s1, o);
                    d0 += __shfl_xor_sync(0xffffffffu, d0, o);
                    d1 += __shfl_xor_sync(0xffffffffu, d1, o);
                }
                if ((lane & 3) == 0) {
                    const int lr = m0 + mf * 16 + (lane >> 2);
                    sred[lr * 4 + nw]              = s0;
                    sred[(lr + 8) * 4 + nw]        = s1;
                    sred[TM * 4 + lr * 4 + nw]       = d0;
                    sred[TM * 4 + (lr + 8) * 4 + nw] = d1;
                }
            }
        }
        __syncthreads();   // protects A smem overwrite AND sred

        if (!isU && tid < TM) {
            const int r = row0 + tid;
            if (r < n) {
                ssrc[r] = sred[tid * 4 + 0] + sred[tid * 4 + 1]
                        + sred[tid * 4 + 2] + sred[tid * 4 + 3];
                sdst[r] = sred[TM * 4 + tid * 4 + 0] + sred[TM * 4 + tid * 4 + 1]
                        + sred[TM * 4 + tid * 4 + 2] + sred[TM * 4 + tid * 4 + 3];
            }
        }
    }
}

// ---------------- attention + aggregation (fp16 gather) ----------------
__global__ __launch_bounds__(256)
void attn_agg_kernel(const __half* __restrict__ z, const __half* __restrict__ zi,
                     const float* __restrict__ ssrc, const float* __restrict__ sdst,
                     const float* __restrict__ edge_d, const int* __restrict__ edge_src,
                     const float* __restrict__ Wv, const float* __restrict__ avec,
                     float* __restrict__ out, int n)
{
    const int node = (blockIdx.x * blockDim.x + threadIdx.x) >> 5;
    const int lane = threadIdx.x & 31;
    if (node >= n) return;

    const float c = Wv[0] * avec[2 * DIM];

    int   src = 0;
    float sc  = -1e30f;
    if (lane < DEG) {
        int e = node * DEG + lane;
        src   = edge_src[e];
        float s = ssrc[src] + sdst[node] + c * edge_d[e];
        sc = (s >= 0.f) ? s : 0.01f * s;
    }
    float m = sc;
    #pragma unroll
    for (int o = 8; o > 0; o >>= 1) m = fmaxf(m, __shfl_xor_sync(0xffffffffu, m, o));
    float ex = (lane < DEG) ? __expf(sc - m) : 0.f;
    float ssum = ex;
    #pragma unroll
    for (int o = 8; o > 0; o >>= 1) ssum += __shfl_xor_sync(0xffffffffu, ssum, o);
    float alpha = ex / ssum;

    float al[DEG];
    int   sr[DEG];
    #pragma unroll
    for (int e = 0; e < DEG; e++) {
        al[e] = __shfl_sync(0xffffffffu, alpha, e);
        sr[e] = __shfl_sync(0xffffffffu, src,   e);
    }

    // zi base: 4 halves per lane (cols lane*4 .. lane*4+3)
    float4 acc;
    {
        uint2 v = *((const uint2*)(zi + (size_t)node * DIM) + lane);
        float2 f0 = __half22float2(*(__half2*)&v.x);
        float2 f1 = __half22float2(*(__half2*)&v.y);
        acc = make_float4(f0.x, f0.y, f1.x, f1.y);
    }
    #pragma unroll
    for (int e = 0; e < DEG; e++) {
        uint2 v = *((const uint2*)(z + (size_t)sr[e] * DIM) + lane);
        float2 f0 = __half22float2(*(__half2*)&v.x);
        float2 f1 = __half22float2(*(__half2*)&v.y);
        acc.x = fmaf(al[e], f0.x, acc.x);
        acc.y = fmaf(al[e], f0.y, acc.y);
        acc.z = fmaf(al[e], f1.x, acc.z);
        acc.w = fmaf(al[e], f1.y, acc.w);
    }
    acc.x = fmaxf(acc.x, 0.f);
    acc.y = fmaxf(acc.y, 0.f);
    acc.z = fmaxf(acc.z, 0.f);
    acc.w = fmaxf(acc.w, 0.f);
    *(float4*)(out + (size_t)node * DIM + lane * 4) = acc;
}

extern "C" void kernel_launch(void* const* d_in, const int* in_sizes, int n_in,
                              void* d_out, int out_size)
{
    const float* attr   = (const float*)d_in[0];
    const float* edge_d = (const float*)d_in[1];
    const float* Wv1    = (const float*)d_in[2];
    const float* Ww1    = (const float*)d_in[3];
    const float* Wu1    = (const float*)d_in[4];
    const float* Wa1    = (const float*)d_in[5];
    const float* Wv2    = (const float*)d_in[6];
    const float* Ww2    = (const float*)d_in[7];
    const float* Wu2    = (const float*)d_in[8];
    const float* Wa2    = (const float*)d_in[9];
    const int*   esrc   = (const int*)d_in[10];
    float*       out    = (float*)d_out;

    float *h1p, *ssp, *sdp;
    __half *zp, *zip;
    __nv_bfloat16* wb;
    cudaGetSymbolAddress((void**)&zp,  g_z);
    cudaGetSymbolAddress((void**)&zip, g_zi);
    cudaGetSymbolAddress((void**)&h1p, g_h1);
    cudaGetSymbolAddress((void**)&ssp, g_ssrc);
    cudaGetSymbolAddress((void**)&sdp, g_sdst);
    cudaGetSymbolAddress((void**)&wb,  g_wimg);

    const __nv_bfloat16* w1h = wb + (size_t)0 * DIM * DIM;
    const __nv_bfloat16* w1l = wb + (size_t)1 * DIM * DIM;
    const __nv_bfloat16* u1h = wb + (size_t)2 * DIM * DIM;
    const __nv_bfloat16* u1l = wb + (size_t)3 * DIM * DIM;
    const __nv_bfloat16* w2h = wb + (size_t)4 * DIM * DIM;
    const __nv_bfloat16* w2l = wb + (size_t)5 * DIM * DIM;
    const __nv_bfloat16* u2h = wb + (size_t)6 * DIM * DIM;
    const __nv_bfloat16* u2l = wb + (size_t)7 * DIM * DIM;

    cudaFuncSetAttribute(gemm_split_kernel,
                         cudaFuncAttributeMaxDynamicSharedMemorySize, SM_TOTAL_B);

    const int grid_a = (NN * 32 + 255) / 256;     // 12500

    wconv_kernel<<<4, 256>>>(Ww1, Wu1, Ww2, Wu2);

    gemm_split_kernel<<<2 * GRIDP, 256, SM_TOTAL_B>>>(attr, w1h, w1l, u1h, u1l, Wa1,
                                                      zp, zip, ssp, sdp, NN);
    attn_agg_kernel<<<grid_a, 256>>>(zp, zip, ssp, sdp, edge_d, esrc, Wv1, Wa1, h1p, NN);

    gemm_split_kernel<<<2 * GRIDP, 256, SM_TOTAL_B>>>(h1p, w2h, w2l, u2h, u2l, Wa2,
                                                      zp, zip, ssp, sdp, NN);
    attn_agg_kernel<<<grid_a, 256>>>(zp, zip, ssp, sdp, edge_d, esrc, Wv2, Wa2, out, NN);
}